// round 1
// baseline (speedup 1.0000x reference)
#include <cuda_runtime.h>
#include <math.h>

#define BB 4
#define SS 1024
#define DD 1024
#define HH 16
#define HD 64
#define MROWS (BB*SS)

// ---------------- scratch (device globals; no allocation) ----------------
__device__ float g_local[MROWS*DD];
__device__ float g_globe[MROWS*DD];
__device__ float g_q[MROWS*DD];
__device__ float g_k[MROWS*DD];
__device__ float g_v[MROWS*DD];
__device__ float g_attn[MROWS*DD];
__device__ float g_gout[MROWS*DD];
__device__ float g_lout[MROWS*DD];
__device__ float g_base[BB];

struct SpanParams {
    int win, span_len, local_max;
    float span_mean, temp;
};
__device__ SpanParams g_params;

// ---------------- LayerNorm (writes both local and globe) ----------------
__global__ void ln_kernel(const float* __restrict__ x,
                          const float* __restrict__ ga, const float* __restrict__ ba,
                          const float* __restrict__ gb, const float* __restrict__ bb)
{
    __shared__ float red[256];
    int row = blockIdx.x;
    int t = threadIdx.x;
    const float* xr = x + (size_t)row * DD;
    float v[4];
    float s = 0.f;
#pragma unroll
    for (int k = 0; k < 4; k++) { v[k] = xr[t + 256*k]; s += v[k]; }
    red[t] = s; __syncthreads();
    for (int o = 128; o > 0; o >>= 1) { if (t < o) red[t] += red[t+o]; __syncthreads(); }
    float mean = red[0] * (1.0f/DD);
    __syncthreads();
    float s2 = 0.f;
#pragma unroll
    for (int k = 0; k < 4; k++) { float d0 = v[k]-mean; s2 += d0*d0; }
    red[t] = s2; __syncthreads();
    for (int o = 128; o > 0; o >>= 1) { if (t < o) red[t] += red[t+o]; __syncthreads(); }
    float rs = rsqrtf(red[0]*(1.0f/DD) + 1e-5f);
#pragma unroll
    for (int k = 0; k < 4; k++) {
        int c = t + 256*k;
        float nh = (v[k]-mean)*rs;
        g_local[(size_t)row*DD + c] = nh*ga[c] + ba[c];
        g_globe[(size_t)row*DD + c] = nh*gb[c] + bb[c];
    }
}

// ---------------- SGEMM: C[M,N] = A[M,K] @ W[N, koff:koff+K]^T (+bias / +=) --
// W row stride = ldw. 128x128 block tile, BK=8, 256 threads, 8x8 micro tile.
__global__ void __launch_bounds__(256) gemm_rk(const float* __restrict__ A,
                                               const float* __restrict__ W,
                                               const float* __restrict__ bias,
                                               float* __restrict__ C,
                                               int N, int K, int ldw, int koff,
                                               int accumulate)
{
    __shared__ float As[8][128];
    __shared__ float Bs[8][128];
    int bm = blockIdx.y * 128, bn = blockIdx.x * 128;
    int t = threadIdx.x;
    int lr = t >> 1;
    int lk = (t & 1) * 4;
    int tx = t & 15, ty = t >> 4;
    float acc[8][8];
#pragma unroll
    for (int i = 0; i < 8; i++)
#pragma unroll
        for (int j = 0; j < 8; j++) acc[i][j] = 0.f;

    const float* Aptr = A + (size_t)(bm + lr) * K + lk;
    const float* Wptr = W + (size_t)(bn + lr) * ldw + koff + lk;

    for (int k0 = 0; k0 < K; k0 += 8) {
        float4 a4 = *(const float4*)(Aptr + k0);
        float4 b4 = *(const float4*)(Wptr + k0);
        As[lk+0][lr]=a4.x; As[lk+1][lr]=a4.y; As[lk+2][lr]=a4.z; As[lk+3][lr]=a4.w;
        Bs[lk+0][lr]=b4.x; Bs[lk+1][lr]=b4.y; Bs[lk+2][lr]=b4.z; Bs[lk+3][lr]=b4.w;
        __syncthreads();
#pragma unroll
        for (int kk = 0; kk < 8; kk++) {
            float a[8], b[8];
#pragma unroll
            for (int i = 0; i < 8; i++) a[i] = As[kk][ty*8 + i];
#pragma unroll
            for (int j = 0; j < 8; j++) b[j] = Bs[kk][tx*8 + j];
#pragma unroll
            for (int i = 0; i < 8; i++)
#pragma unroll
                for (int j = 0; j < 8; j++) acc[i][j] += a[i]*b[j];
        }
        __syncthreads();
    }
#pragma unroll
    for (int i = 0; i < 8; i++) {
        int row = bm + ty*8 + i;
#pragma unroll
        for (int j = 0; j < 8; j++) {
            int col = bn + tx*8 + j;
            size_t idx = (size_t)row * N + col;
            float r = acc[i][j];
            if (accumulate) C[idx] += r;
            else            C[idx] = r + (bias ? bias[col] : 0.f);
        }
    }
}

// ---------------- Global causal attention (flash, Q-tile=32, K-tile=64) ----
__global__ void __launch_bounds__(256) attn_global_kernel()
{
    __shared__ float Qs[32][65];
    __shared__ float Ks[64][65];   // reused for V
    __shared__ float Ss[32][65];
    __shared__ float m_s[32], l_s[32], alpha_s[32];

    int qt = blockIdx.x;            // 0..31
    int bh = blockIdx.y;            // 0..63
    int b = bh >> 4, h = bh & 15;
    int t = threadIdx.x;
    int tx = t & 15, ty = t >> 4;
    int q0 = qt * 32;
    size_t base = (size_t)b * SS * DD + h * HD;

    {
        int col = tx * 4;
#pragma unroll
        for (int rr = 0; rr < 2; rr++) {
            int r = ty + rr*16;
            float4 qv = *(const float4*)(g_q + base + (size_t)(q0 + r) * DD + col);
            Qs[r][col+0]=qv.x; Qs[r][col+1]=qv.y; Qs[r][col+2]=qv.z; Qs[r][col+3]=qv.w;
        }
    }
    if (t < 32) { m_s[t] = -3.0e38f; l_s[t] = 0.f; }
    float accO[2][4];
#pragma unroll
    for (int i = 0; i < 2; i++)
#pragma unroll
        for (int j = 0; j < 4; j++) accO[i][j] = 0.f;

    int ktmax = (q0 + 31) >> 6;
    __syncthreads();

    for (int kt = 0; kt <= ktmax; kt++) {
        {   // load K tile
            int col = tx * 4;
#pragma unroll
            for (int rr = 0; rr < 4; rr++) {
                int r = ty + rr*16;
                float4 kv = *(const float4*)(g_k + base + (size_t)(kt*64 + r) * DD + col);
                Ks[r][col+0]=kv.x; Ks[r][col+1]=kv.y; Ks[r][col+2]=kv.z; Ks[r][col+3]=kv.w;
            }
        }
        __syncthreads();
        // scores (2x4 per thread)
        float sacc[2][4];
#pragma unroll
        for (int i = 0; i < 2; i++)
#pragma unroll
            for (int j = 0; j < 4; j++) sacc[i][j] = 0.f;
#pragma unroll 8
        for (int kk = 0; kk < 64; kk++) {
            float qv0 = Qs[2*ty+0][kk];
            float qv1 = Qs[2*ty+1][kk];
#pragma unroll
            for (int j = 0; j < 4; j++) {
                float kv = Ks[4*tx+j][kk];
                sacc[0][j] += qv0*kv;
                sacc[1][j] += qv1*kv;
            }
        }
#pragma unroll
        for (int i = 0; i < 2; i++) {
            int qrow = q0 + 2*ty + i;
#pragma unroll
            for (int j = 0; j < 4; j++) {
                int krow = kt*64 + 4*tx + j;
                float sv = sacc[i][j] * 0.125f;
                if (krow > qrow) sv = -1.0e30f;
                Ss[2*ty+i][4*tx+j] = sv;
            }
        }
        __syncthreads();
        {   // load V into Ks (K no longer needed)
            int col = tx * 4;
#pragma unroll
            for (int rr = 0; rr < 4; rr++) {
                int r = ty + rr*16;
                float4 vv = *(const float4*)(g_v + base + (size_t)(kt*64 + r) * DD + col);
                Ks[r][col+0]=vv.x; Ks[r][col+1]=vv.y; Ks[r][col+2]=vv.z; Ks[r][col+3]=vv.w;
            }
        }
        if (t < 32) {  // online softmax for row t
            float mo = m_s[t];
            float mx = mo;
#pragma unroll 8
            for (int c = 0; c < 64; c++) mx = fmaxf(mx, Ss[t][c]);
            float alpha = expf(mo - mx);
            float sum = 0.f;
#pragma unroll 8
            for (int c = 0; c < 64; c++) { float e = expf(Ss[t][c]-mx); Ss[t][c] = e; sum += e; }
            m_s[t] = mx; l_s[t] = l_s[t]*alpha + sum; alpha_s[t] = alpha;
        }
        __syncthreads();
        // O update
#pragma unroll
        for (int i = 0; i < 2; i++) {
            float al = alpha_s[2*ty+i];
#pragma unroll
            for (int j = 0; j < 4; j++) accO[i][j] *= al;
        }
#pragma unroll 4
        for (int c = 0; c < 64; c++) {
            float p0 = Ss[2*ty+0][c];
            float p1 = Ss[2*ty+1][c];
#pragma unroll
            for (int j = 0; j < 4; j++) {
                float vv = Ks[c][4*tx+j];
                accO[0][j] += p0*vv;
                accO[1][j] += p1*vv;
            }
        }
        __syncthreads();
    }
#pragma unroll
    for (int i = 0; i < 2; i++) {
        int r = 2*ty + i;
        float inv = 1.f / l_s[r];
#pragma unroll
        for (int j = 0; j < 4; j++)
            g_attn[base + (size_t)(q0 + r) * DD + 4*tx + j] = accO[i][j] * inv;
    }
}

// ---------------- Predictor: base_scale[b] = sigmoid(mean_s(gout)·Wp + bp) --
__global__ void predictor_kernel(const float* __restrict__ Wp, const float* __restrict__ bp)
{
    __shared__ float red[256];
    int b = blockIdx.x;
    int t = threadIdx.x;
    float cs0=0.f, cs1=0.f, cs2=0.f, cs3=0.f;
    const float* p0 = g_gout + (size_t)b * SS * DD + t;
    for (int s = 0; s < SS; s++) {
        const float* p = p0 + (size_t)s * DD;
        cs0 += p[0]; cs1 += p[256]; cs2 += p[512]; cs3 += p[768];
    }
    float part = (cs0*(1.0f/SS))*Wp[t]
               + (cs1*(1.0f/SS))*Wp[t+256]
               + (cs2*(1.0f/SS))*Wp[t+512]
               + (cs3*(1.0f/SS))*Wp[t+768];
    red[t] = part; __syncthreads();
    for (int o = 128; o > 0; o >>= 1) { if (t < o) red[t] += red[t+o]; __syncthreads(); }
    if (t == 0) {
        float z = red[0] + bp[0];
        g_base[b] = 1.f / (1.f + expf(-z));
    }
}

// ---------------- Span params (mirrors Python float64 int() truncation) ----
__global__ void params_kernel()
{
    float smf = (g_base[0] + g_base[1] + g_base[2] + g_base[3]) * 0.25f;
    double sm = (double)smf;
    int win = (int)(256.0 * sm);      if (win < 1) win = 1;
    int span_len = (int)(512.0 * sm); if (span_len < 1) span_len = 1;
    int lm = 512;
    if (span_len < lm) lm = span_len;
    if (win < lm) lm = win;
    g_params.win = win;
    g_params.span_len = span_len;
    g_params.local_max = lm;
    g_params.span_mean = smf;
    g_params.temp = (float)(1.0 + 0.01 * (1.0 - sm));
}

__global__ void zero_kernel(float4* p, int n4)
{
    int i = blockIdx.x * blockDim.x + threadIdx.x;
    if (i < n4) p[i] = make_float4(0.f, 0.f, 0.f, 0.f);
}

// ---------------- Local span attention (K == V, persistent over windows) ----
__global__ void __launch_bounds__(256) attn_local_kernel()
{
    __shared__ float Qs[32][65];
    __shared__ float Ks[64][65];   // keys == values (same rows of g_local)
    __shared__ float Ss[32][65];
    __shared__ float m_s[32], l_s[32], alpha_s[32];

    SpanParams p = g_params;
    int bh = blockIdx.x;  int b = bh >> 4, h = bh & 15;
    int qt = blockIdx.y;  // 0..7 -> q0 = 32*qt (eff <= 255)
    int t = threadIdx.x;
    int tx = t & 15, ty = t >> 4;
    size_t base = (size_t)b * SS * DD + h * HD;
    float sc = 0.35355339059327373f / p.temp;   // 64^-0.25 / temp

    for (int w = blockIdx.z; w * p.win < SS; w += (int)gridDim.z) {
        int st = w * p.win;
        int en = st + p.win; if (en > SS) en = SS;
        int wlen = en - st;
        int ks0 = st - p.span_len + p.win; if (ks0 < 0) ks0 = 0;
        int ke = st + p.span_len; if (ke > SS) ke = SS;
        int klen = ke - ks0;
        int eff = (int)((double)wlen * (double)p.span_mean);
        if (eff > wlen) eff = wlen;
        if (eff > klen) eff = klen;
        if (eff > p.local_max) eff = p.local_max;
        int q0 = qt * 32;
        if (eff <= 0 || q0 >= eff) continue;
        int qcnt = eff - q0; if (qcnt > 32) qcnt = 32;

        {   // load Q tile (rows st+q0 .. )
            int col = tx * 4;
#pragma unroll
            for (int rr = 0; rr < 2; rr++) {
                int r = ty + rr*16;
                float4 qv = make_float4(0.f,0.f,0.f,0.f);
                if (r < qcnt)
                    qv = *(const float4*)(g_local + base + (size_t)(st + q0 + r) * DD + col);
                Qs[r][col+0]=qv.x; Qs[r][col+1]=qv.y; Qs[r][col+2]=qv.z; Qs[r][col+3]=qv.w;
            }
        }
        if (t < 32) { m_s[t] = -3.0e38f; l_s[t] = 0.f; }
        float accO[2][4];
#pragma unroll
        for (int i = 0; i < 2; i++)
#pragma unroll
            for (int j = 0; j < 4; j++) accO[i][j] = 0.f;
        __syncthreads();

        int nkt = (eff + 63) >> 6;
        for (int kt = 0; kt < nkt; kt++) {
            {   // load K(=V) tile
                int col = tx * 4;
#pragma unroll
                for (int rr = 0; rr < 4; rr++) {
                    int r = ty + rr*16;
                    float4 kv = make_float4(0.f,0.f,0.f,0.f);
                    if (kt*64 + r < eff)
                        kv = *(const float4*)(g_local + base + (size_t)(ks0 + kt*64 + r) * DD + col);
                    Ks[r][col+0]=kv.x; Ks[r][col+1]=kv.y; Ks[r][col+2]=kv.z; Ks[r][col+3]=kv.w;
                }
            }
            __syncthreads();
            float sacc[2][4];
#pragma unroll
            for (int i = 0; i < 2; i++)
#pragma unroll
                for (int j = 0; j < 4; j++) sacc[i][j] = 0.f;
#pragma unroll 8
            for (int kk = 0; kk < 64; kk++) {
                float qv0 = Qs[2*ty+0][kk];
                float qv1 = Qs[2*ty+1][kk];
#pragma unroll
                for (int j = 0; j < 4; j++) {
                    float kv = Ks[4*tx+j][kk];
                    sacc[0][j] += qv0*kv;
                    sacc[1][j] += qv1*kv;
                }
            }
#pragma unroll
            for (int i = 0; i < 2; i++) {
#pragma unroll
                for (int j = 0; j < 4; j++) {
                    float sv = sacc[i][j] * sc;
                    if (kt*64 + 4*tx + j >= eff) sv = -1.0e30f;
                    Ss[2*ty+i][4*tx+j] = sv;
                }
            }
            __syncthreads();
            if (t < 32) {
                float mo = m_s[t];
                float mx = mo;
#pragma unroll 8
                for (int c = 0; c < 64; c++) mx = fmaxf(mx, Ss[t][c]);
                float alpha = expf(mo - mx);
                float sum = 0.f;
#pragma unroll 8
                for (int c = 0; c < 64; c++) { float e = expf(Ss[t][c]-mx); Ss[t][c] = e; sum += e; }
                m_s[t] = mx; l_s[t] = l_s[t]*alpha + sum; alpha_s[t] = alpha;
            }
            __syncthreads();
#pragma unroll
            for (int i = 0; i < 2; i++) {
                float al = alpha_s[2*ty+i];
#pragma unroll
                for (int j = 0; j < 4; j++) accO[i][j] *= al;
            }
#pragma unroll 4
            for (int c = 0; c < 64; c++) {
                float p0 = Ss[2*ty+0][c];
                float p1 = Ss[2*ty+1][c];
#pragma unroll
                for (int j = 0; j < 4; j++) {
                    float vv = Ks[c][4*tx+j];  // V == K rows
                    accO[0][j] += p0*vv;
                    accO[1][j] += p1*vv;
                }
            }
            __syncthreads();
        }
#pragma unroll
        for (int i = 0; i < 2; i++) {
            int r = 2*ty + i;
            if (r < qcnt) {
                float inv = 1.f / l_s[r];
#pragma unroll
                for (int j = 0; j < 4; j++)
                    g_lout[base + (size_t)(st + q0 + r) * DD + 4*tx + j] = accO[i][j] * inv;
            }
        }
        __syncthreads();   // protect m_s/l_s reinit of next window
    }
}

// ---------------- launch ----------------
extern "C" void kernel_launch(void* const* d_in, const int* in_sizes, int n_in,
                              void* d_out, int out_size)
{
    const float* x     = (const float*)d_in[0];
    const float* ln_ag = (const float*)d_in[1];
    const float* ln_ab = (const float*)d_in[2];
    const float* ln_bg = (const float*)d_in[3];
    const float* ln_bb = (const float*)d_in[4];
    const float* Wq    = (const float*)d_in[5];
    const float* bq    = (const float*)d_in[6];
    const float* Wk    = (const float*)d_in[7];
    const float* Wv    = (const float*)d_in[8];
    const float* bv    = (const float*)d_in[9];
    const float* Wo    = (const float*)d_in[10];
    const float* bo    = (const float*)d_in[11];
    const float* Wp    = (const float*)d_in[12];
    const float* bp    = (const float*)d_in[13];
    const float* Wproj = (const float*)d_in[14];
    const float* bproj = (const float*)d_in[15];
    float* out = (float*)d_out;

    void *p_local, *p_globe, *p_q, *p_k, *p_v, *p_attn, *p_gout, *p_lout;
    cudaGetSymbolAddress(&p_local, g_local);
    cudaGetSymbolAddress(&p_globe, g_globe);
    cudaGetSymbolAddress(&p_q, g_q);
    cudaGetSymbolAddress(&p_k, g_k);
    cudaGetSymbolAddress(&p_v, g_v);
    cudaGetSymbolAddress(&p_attn, g_attn);
    cudaGetSymbolAddress(&p_gout, g_gout);
    cudaGetSymbolAddress(&p_lout, g_lout);

    // 1) LayerNorms
    ln_kernel<<<MROWS, 256>>>(x, ln_ag, ln_ab, ln_bg, ln_bb);

    // 2) Q/K/V projections
    dim3 ggrid(DD/128, MROWS/128);  // (8, 32)
    gemm_rk<<<ggrid, 256>>>((const float*)p_globe, Wq, bq,      (float*)p_q, DD, DD, DD, 0, 0);
    gemm_rk<<<ggrid, 256>>>((const float*)p_globe, Wk, nullptr, (float*)p_k, DD, DD, DD, 0, 0);
    gemm_rk<<<ggrid, 256>>>((const float*)p_globe, Wv, bv,      (float*)p_v, DD, DD, DD, 0, 0);

    // 3) Global causal attention
    attn_global_kernel<<<dim3(SS/32, BB*HH), 256>>>();

    // 4) Output projection of global attention
    gemm_rk<<<ggrid, 256>>>((const float*)p_attn, Wo, bo, (float*)p_gout, DD, DD, DD, 0, 0);

    // 5) Span predictor + params
    predictor_kernel<<<BB, 256>>>(Wp, bp);
    params_kernel<<<1, 1>>>();

    // 6) Local span attention (output pre-zeroed; windows self-scheduled)
    zero_kernel<<<(MROWS*DD/4 + 255)/256, 256>>>((float4*)p_lout, MROWS*DD/4);
    attn_local_kernel<<<dim3(BB*HH, 8, 16), 256>>>();

    // 7) Final projection: out = [local_out, globe_out] @ Wproj^T + bproj
    gemm_rk<<<ggrid, 256>>>((const float*)p_lout, Wproj, bproj,  out, DD, DD, 2*DD, 0,  0);
    gemm_rk<<<ggrid, 256>>>((const float*)p_gout, Wproj, nullptr, out, DD, DD, 2*DD, DD, 1);
}

// round 3
// speedup vs baseline: 1.1325x; 1.1325x over previous
#include <cuda_runtime.h>
#include <math.h>

#define BB 4
#define SS 1024
#define DD 1024
#define HH 16
#define HD 64
#define MROWS (BB*SS)

// ---------------- scratch (device globals; no allocation) ----------------
__device__ float g_local[MROWS*DD];
__device__ float g_globe[MROWS*DD];
__device__ float g_q[MROWS*DD];
__device__ float g_k[MROWS*DD];
__device__ float g_v[MROWS*DD];
__device__ float g_attn[MROWS*DD];
__device__ float g_gout[MROWS*DD];
__device__ float g_lout[MROWS*DD];
__device__ float g_base[BB];

struct SpanParams {
    int win, span_len, local_max;
    float span_mean, temp;
};
__device__ SpanParams g_params;

// ---------------- helpers ----------------
__device__ __forceinline__ float to_tf32(float x) {
    float r;
    asm("cvt.rna.tf32.f32 %0, %1;" : "=f"(r) : "f"(x));
    return r;
}

__device__ __forceinline__ void mma_tf32(float c[4],
                                         unsigned a0, unsigned a1, unsigned a2, unsigned a3,
                                         unsigned b0, unsigned b1)
{
    asm volatile("mma.sync.aligned.m16n8k8.row.col.f32.tf32.tf32.f32 "
                 "{%0,%1,%2,%3}, {%4,%5,%6,%7}, {%8,%9}, {%0,%1,%2,%3};"
                 : "+f"(c[0]), "+f"(c[1]), "+f"(c[2]), "+f"(c[3])
                 : "r"(a0), "r"(a1), "r"(a2), "r"(a3), "r"(b0), "r"(b1));
}

// ---------------- LayerNorm (writes both local and globe) ----------------
__global__ void ln_kernel(const float* __restrict__ x,
                          const float* __restrict__ ga, const float* __restrict__ ba,
                          const float* __restrict__ gb, const float* __restrict__ bb)
{
    __shared__ float red[256];
    int row = blockIdx.x;
    int t = threadIdx.x;
    const float* xr = x + (size_t)row * DD;
    float v[4];
    float s = 0.f;
#pragma unroll
    for (int k = 0; k < 4; k++) { v[k] = xr[t + 256*k]; s += v[k]; }
    red[t] = s; __syncthreads();
    for (int o = 128; o > 0; o >>= 1) { if (t < o) red[t] += red[t+o]; __syncthreads(); }
    float mean = red[0] * (1.0f/DD);
    __syncthreads();
    float s2 = 0.f;
#pragma unroll
    for (int k = 0; k < 4; k++) { float d0 = v[k]-mean; s2 += d0*d0; }
    red[t] = s2; __syncthreads();
    for (int o = 128; o > 0; o >>= 1) { if (t < o) red[t] += red[t+o]; __syncthreads(); }
    float rs = rsqrtf(red[0]*(1.0f/DD) + 1e-5f);
#pragma unroll
    for (int k = 0; k < 4; k++) {
        int c = t + 256*k;
        float nh = (v[k]-mean)*rs;
        g_local[(size_t)row*DD + c] = nh*ga[c] + ba[c];
        g_globe[(size_t)row*DD + c] = nh*gb[c] + bb[c];
    }
}

// ---------------- 3xTF32 tensor-core GEMM (fp32 accuracy) ----------------
// C[M,N] = A[M,K] @ W[N, koff:koff+K]^T (+bias or +=).  W row stride = ldw.
// 128x128 CTA tile, K-chunk 16, 8 warps in 2(m) x 4(n), warp tile 64x32.
// Each operand split v = hi + lo (tf32); acc += hi*hi + hi*lo + lo*hi.
__global__ void __launch_bounds__(256) gemm_3xtf32(const float* __restrict__ A,
                                                   const float* __restrict__ W,
                                                   const float* __restrict__ bias,
                                                   float* __restrict__ C,
                                                   int N, int K, int ldw, int koff,
                                                   int accumulate)
{
    __shared__ float Ah[128][20];
    __shared__ float Al[128][20];
    __shared__ float Bh[128][20];
    __shared__ float Bl[128][20];

    int t = threadIdx.x;
    int wid = t >> 5, lane = t & 31;
    int warp_m = wid >> 2;          // 0..1  (64 rows each)
    int warp_n = wid & 3;           // 0..3  (32 cols each)
    int bm = blockIdx.y * 128, bn = blockIdx.x * 128;

    float acc[4][4][4];
#pragma unroll
    for (int im = 0; im < 4; im++)
#pragma unroll
        for (int in = 0; in < 4; in++)
#pragma unroll
            for (int r = 0; r < 4; r++) acc[im][in][r] = 0.f;

    int lr = t >> 2;           // 0..63
    int lc = (t & 3) * 4;      // 0,4,8,12
    const float* Ag = A + (size_t)(bm + lr) * K + lc;
    const float* Wg = W + (size_t)(bn + lr) * ldw + koff + lc;

    float4 ra[2], rb[2];
#pragma unroll
    for (int i = 0; i < 2; i++) {
        ra[i] = *(const float4*)(Ag + (size_t)(i*64) * K);
        rb[i] = *(const float4*)(Wg + (size_t)(i*64) * ldw);
    }

    for (int k0 = 0; k0 < K; k0 += 16) {
        // stage regs -> smem with hi/lo tf32 split
#pragma unroll
        for (int i = 0; i < 2; i++) {
            int row = lr + i*64;
            float av[4] = {ra[i].x, ra[i].y, ra[i].z, ra[i].w};
            float bv[4] = {rb[i].x, rb[i].y, rb[i].z, rb[i].w};
#pragma unroll
            for (int j = 0; j < 4; j++) {
                float ah = to_tf32(av[j]);
                float bh = to_tf32(bv[j]);
                Ah[row][lc+j] = ah;  Al[row][lc+j] = to_tf32(av[j] - ah);
                Bh[row][lc+j] = bh;  Bl[row][lc+j] = to_tf32(bv[j] - bh);
            }
        }
        __syncthreads();

        // prefetch next chunk
        if (k0 + 16 < K) {
#pragma unroll
            for (int i = 0; i < 2; i++) {
                ra[i] = *(const float4*)(Ag + k0 + 16 + (size_t)(i*64) * K);
                rb[i] = *(const float4*)(Wg + k0 + 16 + (size_t)(i*64) * ldw);
            }
        }

        // 2 k-steps of 8
#pragma unroll
        for (int ks = 0; ks < 2; ks++) {
            int ak = ks*8 + (lane & 3);
            int br = warp_n*32 + (lane >> 2);
            unsigned bhf[4][2], blf[4][2];
#pragma unroll
            for (int in = 0; in < 4; in++) {
                bhf[in][0] = __float_as_uint(Bh[br + in*8][ak    ]);
                bhf[in][1] = __float_as_uint(Bh[br + in*8][ak + 4]);
                blf[in][0] = __float_as_uint(Bl[br + in*8][ak    ]);
                blf[in][1] = __float_as_uint(Bl[br + in*8][ak + 4]);
            }
#pragma unroll
            for (int im = 0; im < 4; im++) {
                int ar = warp_m*64 + im*16 + (lane >> 2);
                unsigned ah0 = __float_as_uint(Ah[ar    ][ak    ]);
                unsigned ah1 = __float_as_uint(Ah[ar + 8][ak    ]);
                unsigned ah2 = __float_as_uint(Ah[ar    ][ak + 4]);
                unsigned ah3 = __float_as_uint(Ah[ar + 8][ak + 4]);
                unsigned al0 = __float_as_uint(Al[ar    ][ak    ]);
                unsigned al1 = __float_as_uint(Al[ar + 8][ak    ]);
                unsigned al2 = __float_as_uint(Al[ar    ][ak + 4]);
                unsigned al3 = __float_as_uint(Al[ar + 8][ak + 4]);
#pragma unroll
                for (int in = 0; in < 4; in++) {
                    mma_tf32(acc[im][in], ah0, ah1, ah2, ah3, bhf[in][0], bhf[in][1]);
                    mma_tf32(acc[im][in], ah0, ah1, ah2, ah3, blf[in][0], blf[in][1]);
                    mma_tf32(acc[im][in], al0, al1, al2, al3, bhf[in][0], bhf[in][1]);
                }
            }
        }
        __syncthreads();
    }

    // epilogue
#pragma unroll
    for (int im = 0; im < 4; im++) {
        int r0 = bm + warp_m*64 + im*16 + (lane >> 2);
#pragma unroll
        for (int in = 0; in < 4; in++) {
            int c0 = bn + warp_n*32 + in*8 + 2*(lane & 3);
            float* C0 = C + (size_t)r0 * N + c0;
            float* C1 = C + (size_t)(r0+8) * N + c0;
            if (accumulate) {
                C0[0] += acc[im][in][0]; C0[1] += acc[im][in][1];
                C1[0] += acc[im][in][2]; C1[1] += acc[im][in][3];
            } else {
                float b0v = bias ? bias[c0]   : 0.f;
                float b1v = bias ? bias[c0+1] : 0.f;
                C0[0] = acc[im][in][0] + b0v; C0[1] = acc[im][in][1] + b1v;
                C1[0] = acc[im][in][2] + b0v; C1[1] = acc[im][in][3] + b1v;
            }
        }
    }
}

// ---------------- Global causal attention (flash, Q-tile=32, K-tile=64) ----
__global__ void __launch_bounds__(256) attn_global_kernel()
{
    __shared__ float Qs[32][65];
    __shared__ float Ks[64][65];   // reused for V
    __shared__ float Ss[32][65];
    __shared__ float m_s[32], l_s[32], alpha_s[32];

    int qt = blockIdx.x;
    int bh = blockIdx.y;
    int b = bh >> 4, h = bh & 15;
    int t = threadIdx.x;
    int tx = t & 15, ty = t >> 4;
    int q0 = qt * 32;
    size_t base = (size_t)b * SS * DD + h * HD;

    {
        int col = tx * 4;
#pragma unroll
        for (int rr = 0; rr < 2; rr++) {
            int r = ty + rr*16;
            float4 qv = *(const float4*)(g_q + base + (size_t)(q0 + r) * DD + col);
            Qs[r][col+0]=qv.x; Qs[r][col+1]=qv.y; Qs[r][col+2]=qv.z; Qs[r][col+3]=qv.w;
        }
    }
    if (t < 32) { m_s[t] = -3.0e38f; l_s[t] = 0.f; }
    float accO[2][4];
#pragma unroll
    for (int i = 0; i < 2; i++)
#pragma unroll
        for (int j = 0; j < 4; j++) accO[i][j] = 0.f;

    int ktmax = (q0 + 31) >> 6;
    __syncthreads();

    for (int kt = 0; kt <= ktmax; kt++) {
        {   // load K tile
            int col = tx * 4;
#pragma unroll
            for (int rr = 0; rr < 4; rr++) {
                int r = ty + rr*16;
                float4 kv = *(const float4*)(g_k + base + (size_t)(kt*64 + r) * DD + col);
                Ks[r][col+0]=kv.x; Ks[r][col+1]=kv.y; Ks[r][col+2]=kv.z; Ks[r][col+3]=kv.w;
            }
        }
        __syncthreads();
        float sacc[2][4];
#pragma unroll
        for (int i = 0; i < 2; i++)
#pragma unroll
            for (int j = 0; j < 4; j++) sacc[i][j] = 0.f;
#pragma unroll 8
        for (int kk = 0; kk < 64; kk++) {
            float qv0 = Qs[2*ty+0][kk];
            float qv1 = Qs[2*ty+1][kk];
#pragma unroll
            for (int j = 0; j < 4; j++) {
                float kv = Ks[4*tx+j][kk];
                sacc[0][j] += qv0*kv;
                sacc[1][j] += qv1*kv;
            }
        }
#pragma unroll
        for (int i = 0; i < 2; i++) {
            int qrow = q0 + 2*ty + i;
#pragma unroll
            for (int j = 0; j < 4; j++) {
                int krow = kt*64 + 4*tx + j;
                float sv = sacc[i][j] * 0.125f;
                if (krow > qrow) sv = -1.0e30f;
                Ss[2*ty+i][4*tx+j] = sv;
            }
        }
        __syncthreads();
        {   // load V into Ks (K no longer needed)
            int col = tx * 4;
#pragma unroll
            for (int rr = 0; rr < 4; rr++) {
                int r = ty + rr*16;
                float4 vv = *(const float4*)(g_v + base + (size_t)(kt*64 + r) * DD + col);
                Ks[r][col+0]=vv.x; Ks[r][col+1]=vv.y; Ks[r][col+2]=vv.z; Ks[r][col+3]=vv.w;
            }
        }
        {   // online softmax: 8 lanes per row, 32 rows
            int row = t >> 3, sub = t & 7;
            float mo = m_s[row];
            float mx = mo;
#pragma unroll
            for (int c = sub; c < 64; c += 8) mx = fmaxf(mx, Ss[row][c]);
            mx = fmaxf(mx, __shfl_xor_sync(0xffffffffu, mx, 1));
            mx = fmaxf(mx, __shfl_xor_sync(0xffffffffu, mx, 2));
            mx = fmaxf(mx, __shfl_xor_sync(0xffffffffu, mx, 4));
            float sum = 0.f;
#pragma unroll
            for (int c = sub; c < 64; c += 8) {
                float e = __expf(Ss[row][c] - mx);
                Ss[row][c] = e; sum += e;
            }
            sum += __shfl_xor_sync(0xffffffffu, sum, 1);
            sum += __shfl_xor_sync(0xffffffffu, sum, 2);
            sum += __shfl_xor_sync(0xffffffffu, sum, 4);
            if (sub == 0) {
                float alpha = __expf(mo - mx);
                m_s[row] = mx;
                l_s[row] = l_s[row]*alpha + sum;
                alpha_s[row] = alpha;
            }
        }
        __syncthreads();
#pragma unroll
        for (int i = 0; i < 2; i++) {
            float al = alpha_s[2*ty+i];
#pragma unroll
            for (int j = 0; j < 4; j++) accO[i][j] *= al;
        }
#pragma unroll 4
        for (int c = 0; c < 64; c++) {
            float p0 = Ss[2*ty+0][c];
            float p1 = Ss[2*ty+1][c];
#pragma unroll
            for (int j = 0; j < 4; j++) {
                float vv = Ks[c][4*tx+j];
                accO[0][j] += p0*vv;
                accO[1][j] += p1*vv;
            }
        }
        __syncthreads();
    }
#pragma unroll
    for (int i = 0; i < 2; i++) {
        int r = 2*ty + i;
        float inv = 1.f / l_s[r];
#pragma unroll
        for (int j = 0; j < 4; j++)
            g_attn[base + (size_t)(q0 + r) * DD + 4*tx + j] = accO[i][j] * inv;
    }
}

// ---------------- Predictor ----------------
__global__ void predictor_kernel(const float* __restrict__ Wp, const float* __restrict__ bp)
{
    __shared__ float red[256];
    int b = blockIdx.x;
    int t = threadIdx.x;
    float cs0=0.f, cs1=0.f, cs2=0.f, cs3=0.f;
    const float* p0 = g_gout + (size_t)b * SS * DD + t;
    for (int s = 0; s < SS; s++) {
        const float* p = p0 + (size_t)s * DD;
        cs0 += p[0]; cs1 += p[256]; cs2 += p[512]; cs3 += p[768];
    }
    float part = (cs0*(1.0f/SS))*Wp[t]
               + (cs1*(1.0f/SS))*Wp[t+256]
               + (cs2*(1.0f/SS))*Wp[t+512]
               + (cs3*(1.0f/SS))*Wp[t+768];
    red[t] = part; __syncthreads();
    for (int o = 128; o > 0; o >>= 1) { if (t < o) red[t] += red[t+o]; __syncthreads(); }
    if (t == 0) {
        float z = red[0] + bp[0];
        g_base[b] = 1.f / (1.f + expf(-z));
    }
}

// ---------------- Span params (mirrors Python float64 int() truncation) ----
__global__ void params_kernel()
{
    float smf = (g_base[0] + g_base[1] + g_base[2] + g_base[3]) * 0.25f;
    double sm = (double)smf;
    int win = (int)(256.0 * sm);      if (win < 1) win = 1;
    int span_len = (int)(512.0 * sm); if (span_len < 1) span_len = 1;
    int lm = 512;
    if (span_len < lm) lm = span_len;
    if (win < lm) lm = win;
    g_params.win = win;
    g_params.span_len = span_len;
    g_params.local_max = lm;
    g_params.span_mean = smf;
    g_params.temp = (float)(1.0 + 0.01 * (1.0 - sm));
}

__global__ void zero_kernel(float4* p, int n4)
{
    int i = blockIdx.x * blockDim.x + threadIdx.x;
    if (i < n4) p[i] = make_float4(0.f, 0.f, 0.f, 0.f);
}

// ---------------- Local span attention (K == V, persistent over windows) ----
__global__ void __launch_bounds__(256) attn_local_kernel()
{
    __shared__ float Qs[32][65];
    __shared__ float Ks[64][65];
    __shared__ float Ss[32][65];
    __shared__ float m_s[32], l_s[32], alpha_s[32];

    SpanParams p = g_params;
    int bh = blockIdx.x;  int b = bh >> 4, h = bh & 15;
    int qt = blockIdx.y;
    int t = threadIdx.x;
    int tx = t & 15, ty = t >> 4;
    size_t base = (size_t)b * SS * DD + h * HD;
    float sc = 0.35355339059327373f / p.temp;

    for (int w = blockIdx.z; w * p.win < SS; w += (int)gridDim.z) {
        int st = w * p.win;
        int en = st + p.win; if (en > SS) en = SS;
        int wlen = en - st;
        int ks0 = st - p.span_len + p.win; if (ks0 < 0) ks0 = 0;
        int ke = st + p.span_len; if (ke > SS) ke = SS;
        int klen = ke - ks0;
        int eff = (int)((double)wlen * (double)p.span_mean);
        if (eff > wlen) eff = wlen;
        if (eff > klen) eff = klen;
        if (eff > p.local_max) eff = p.local_max;
        int q0 = qt * 32;
        if (eff <= 0 || q0 >= eff) continue;
        int qcnt = eff - q0; if (qcnt > 32) qcnt = 32;

        {
            int col = tx * 4;
#pragma unroll
            for (int rr = 0; rr < 2; rr++) {
                int r = ty + rr*16;
                float4 qv = make_float4(0.f,0.f,0.f,0.f);
                if (r < qcnt)
                    qv = *(const float4*)(g_local + base + (size_t)(st + q0 + r) * DD + col);
                Qs[r][col+0]=qv.x; Qs[r][col+1]=qv.y; Qs[r][col+2]=qv.z; Qs[r][col+3]=qv.w;
            }
        }
        if (t < 32) { m_s[t] = -3.0e38f; l_s[t] = 0.f; }
        float accO[2][4];
#pragma unroll
        for (int i = 0; i < 2; i++)
#pragma unroll
            for (int j = 0; j < 4; j++) accO[i][j] = 0.f;
        __syncthreads();

        int nkt = (eff + 63) >> 6;
        for (int kt = 0; kt < nkt; kt++) {
            {
                int col = tx * 4;
#pragma unroll
                for (int rr = 0; rr < 4; rr++) {
                    int r = ty + rr*16;
                    float4 kv = make_float4(0.f,0.f,0.f,0.f);
                    if (kt*64 + r < eff)
                        kv = *(const float4*)(g_local + base + (size_t)(ks0 + kt*64 + r) * DD + col);
                    Ks[r][col+0]=kv.x; Ks[r][col+1]=kv.y; Ks[r][col+2]=kv.z; Ks[r][col+3]=kv.w;
                }
            }
            __syncthreads();
            float sacc[2][4];
#pragma unroll
            for (int i = 0; i < 2; i++)
#pragma unroll
                for (int j = 0; j < 4; j++) sacc[i][j] = 0.f;
#pragma unroll 8
            for (int kk = 0; kk < 64; kk++) {
                float qv0 = Qs[2*ty+0][kk];
                float qv1 = Qs[2*ty+1][kk];
#pragma unroll
                for (int j = 0; j < 4; j++) {
                    float kv = Ks[4*tx+j][kk];
                    sacc[0][j] += qv0*kv;
                    sacc[1][j] += qv1*kv;
                }
            }
#pragma unroll
            for (int i = 0; i < 2; i++) {
#pragma unroll
                for (int j = 0; j < 4; j++) {
                    float sv = sacc[i][j] * sc;
                    if (kt*64 + 4*tx + j >= eff) sv = -1.0e30f;
                    Ss[2*ty+i][4*tx+j] = sv;
                }
            }
            __syncthreads();
            {   // parallel online softmax
                int row = t >> 3, sub = t & 7;
                float mo = m_s[row];
                float mx = mo;
#pragma unroll
                for (int c = sub; c < 64; c += 8) mx = fmaxf(mx, Ss[row][c]);
                mx = fmaxf(mx, __shfl_xor_sync(0xffffffffu, mx, 1));
                mx = fmaxf(mx, __shfl_xor_sync(0xffffffffu, mx, 2));
                mx = fmaxf(mx, __shfl_xor_sync(0xffffffffu, mx, 4));
                float sum = 0.f;
#pragma unroll
                for (int c = sub; c < 64; c += 8) {
                    float e = __expf(Ss[row][c] - mx);
                    Ss[row][c] = e; sum += e;
                }
                sum += __shfl_xor_sync(0xffffffffu, sum, 1);
                sum += __shfl_xor_sync(0xffffffffu, sum, 2);
                sum += __shfl_xor_sync(0xffffffffu, sum, 4);
                if (sub == 0) {
                    float alpha = __expf(mo - mx);
                    m_s[row] = mx;
                    l_s[row] = l_s[row]*alpha + sum;
                    alpha_s[row] = alpha;
                }
            }
            __syncthreads();
#pragma unroll
            for (int i = 0; i < 2; i++) {
                float al = alpha_s[2*ty+i];
#pragma unroll
                for (int j = 0; j < 4; j++) accO[i][j] *= al;
            }
#pragma unroll 4
            for (int c = 0; c < 64; c++) {
                float p0 = Ss[2*ty+0][c];
                float p1 = Ss[2*ty+1][c];
#pragma unroll
                for (int j = 0; j < 4; j++) {
                    float vv = Ks[c][4*tx+j];
                    accO[0][j] += p0*vv;
                    accO[1][j] += p1*vv;
                }
            }
            __syncthreads();
        }
#pragma unroll
        for (int i = 0; i < 2; i++) {
            int r = 2*ty + i;
            if (r < qcnt) {
                float inv = 1.f / l_s[r];
#pragma unroll
                for (int j = 0; j < 4; j++)
                    g_lout[base + (size_t)(st + q0 + r) * DD + 4*tx + j] = accO[i][j] * inv;
            }
        }
        __syncthreads();
    }
}

// ---------------- launch ----------------
extern "C" void kernel_launch(void* const* d_in, const int* in_sizes, int n_in,
                              void* d_out, int out_size)
{
    const float* x     = (const float*)d_in[0];
    const float* ln_ag = (const float*)d_in[1];
    const float* ln_ab = (const float*)d_in[2];
    const float* ln_bg = (const float*)d_in[3];
    const float* ln_bb = (const float*)d_in[4];
    const float* Wq    = (const float*)d_in[5];
    const float* bq    = (const float*)d_in[6];
    const float* Wk    = (const float*)d_in[7];
    const float* Wv    = (const float*)d_in[8];
    const float* bv    = (const float*)d_in[9];
    const float* Wo    = (const float*)d_in[10];
    const float* bo    = (const float*)d_in[11];
    const float* Wp    = (const float*)d_in[12];
    const float* bp    = (const float*)d_in[13];
    const float* Wproj = (const float*)d_in[14];
    const float* bproj = (const float*)d_in[15];
    float* out = (float*)d_out;

    void *p_local, *p_globe, *p_q, *p_k, *p_v, *p_attn, *p_gout, *p_lout;
    cudaGetSymbolAddress(&p_local, g_local);
    cudaGetSymbolAddress(&p_globe, g_globe);
    cudaGetSymbolAddress(&p_q, g_q);
    cudaGetSymbolAddress(&p_k, g_k);
    cudaGetSymbolAddress(&p_v, g_v);
    cudaGetSymbolAddress(&p_attn, g_attn);
    cudaGetSymbolAddress(&p_gout, g_gout);
    cudaGetSymbolAddress(&p_lout, g_lout);

    // 1) LayerNorms
    ln_kernel<<<MROWS, 256>>>(x, ln_ag, ln_ab, ln_bg, ln_bb);

    // 2) Q/K/V projections (3xTF32 tensor cores, fp32 accuracy)
    dim3 ggrid(DD/128, MROWS/128);  // (8, 32)
    gemm_3xtf32<<<ggrid, 256>>>((const float*)p_globe, Wq, bq,      (float*)p_q, DD, DD, DD, 0, 0);
    gemm_3xtf32<<<ggrid, 256>>>((const float*)p_globe, Wk, nullptr, (float*)p_k, DD, DD, DD, 0, 0);
    gemm_3xtf32<<<ggrid, 256>>>((const float*)p_globe, Wv, bv,      (float*)p_v, DD, DD, DD, 0, 0);

    // 3) Global causal attention
    attn_global_kernel<<<dim3(SS/32, BB*HH), 256>>>();

    // 4) Output projection
    gemm_3xtf32<<<ggrid, 256>>>((const float*)p_attn, Wo, bo, (float*)p_gout, DD, DD, DD, 0, 0);

    // 5) Span predictor + params
    predictor_kernel<<<BB, 256>>>(Wp, bp);
    params_kernel<<<1, 1>>>();

    // 6) Local span attention
    zero_kernel<<<(MROWS*DD/4 + 255)/256, 256>>>((float4*)p_lout, MROWS*DD/4);
    attn_local_kernel<<<dim3(BB*HH, 8, 16), 256>>>();

    // 7) Final projection: out = [local_out, globe_out] @ Wproj^T + bproj
    gemm_3xtf32<<<ggrid, 256>>>((const float*)p_lout, Wproj, bproj,  out, DD, DD, 2*DD, 0,  0);
    gemm_3xtf32<<<ggrid, 256>>>((const float*)p_gout, Wproj, nullptr, out, DD, DD, 2*DD, DD, 1);
}

// round 4
// speedup vs baseline: 1.7058x; 1.5061x over previous
#include <cuda_runtime.h>
#include <math.h>

#define BB 4
#define SS 1024
#define DD 1024
#define HH 16
#define HD 64
#define MROWS (BB*SS)

// ---------------- scratch (device globals; no allocation) ----------------
__device__ float g_local[MROWS*DD];
__device__ float g_globe[MROWS*DD];
__device__ float g_q[MROWS*DD];
__device__ float g_k[MROWS*DD];
__device__ float g_v[MROWS*DD];      // stored TRANSPOSED: [b][h][d][s]
__device__ float g_attn[MROWS*DD];
__device__ float g_gout[MROWS*DD];
__device__ float g_lout[MROWS*DD];
__device__ float g_base[BB];
__device__ float g_pp[BB*16*DD];     // predictor partials

struct SpanParams {
    int win, span_len, local_max;
    float span_mean, temp;
};
__device__ SpanParams g_params;

// ---------------- helpers ----------------
__device__ __forceinline__ float to_tf32(float x) {
    float r;
    asm("cvt.rna.tf32.f32 %0, %1;" : "=f"(r) : "f"(x));
    return r;
}

__device__ __forceinline__ void mma_tf32(float c[4],
                                         unsigned a0, unsigned a1, unsigned a2, unsigned a3,
                                         unsigned b0, unsigned b1)
{
    asm volatile("mma.sync.aligned.m16n8k8.row.col.f32.tf32.tf32.f32 "
                 "{%0,%1,%2,%3}, {%4,%5,%6,%7}, {%8,%9}, {%0,%1,%2,%3};"
                 : "+f"(c[0]), "+f"(c[1]), "+f"(c[2]), "+f"(c[3])
                 : "r"(a0), "r"(a1), "r"(a2), "r"(a3), "r"(b0), "r"(b1));
}

// ---------------- LayerNorm (writes both local and globe) ----------------
__global__ void ln_kernel(const float* __restrict__ x,
                          const float* __restrict__ ga, const float* __restrict__ ba,
                          const float* __restrict__ gb, const float* __restrict__ bb)
{
    __shared__ float red[256];
    int row = blockIdx.x;
    int t = threadIdx.x;
    const float* xr = x + (size_t)row * DD;
    float v[4];
    float s = 0.f;
#pragma unroll
    for (int k = 0; k < 4; k++) { v[k] = xr[t + 256*k]; s += v[k]; }
    red[t] = s; __syncthreads();
    for (int o = 128; o > 0; o >>= 1) { if (t < o) red[t] += red[t+o]; __syncthreads(); }
    float mean = red[0] * (1.0f/DD);
    __syncthreads();
    float s2 = 0.f;
#pragma unroll
    for (int k = 0; k < 4; k++) { float d0 = v[k]-mean; s2 += d0*d0; }
    red[t] = s2; __syncthreads();
    for (int o = 128; o > 0; o >>= 1) { if (t < o) red[t] += red[t+o]; __syncthreads(); }
    float rs = rsqrtf(red[0]*(1.0f/DD) + 1e-5f);
#pragma unroll
    for (int k = 0; k < 4; k++) {
        int c = t + 256*k;
        float nh = (v[k]-mean)*rs;
        g_local[(size_t)row*DD + c] = nh*ga[c] + ba[c];
        g_globe[(size_t)row*DD + c] = nh*gb[c] + bb[c];
    }
}

// ---------------- 3xTF32 tensor-core GEMM, double-buffered ----------------
// C[M,N] = A[M,K] @ W[N, koff:koff+K]^T (+bias or +=).  W row stride = ldw.
// 128x128 CTA tile, K-chunk 16, 8 warps 2(m)x4(n), warp tile 64x32.
// transv: write C transposed per (b,h): C_t[((m>>10)*16+(n>>6))*64+(n&63)]*1024 + (m&1023)
#define GP 2560                 // plane size (floats): 128*20
#define AHs(b,r,c) dsm[(b)*4*GP          + (r)*20 + (c)]
#define ALs(b,r,c) dsm[(b)*4*GP + GP     + (r)*20 + (c)]
#define BHs(b,r,c) dsm[(b)*4*GP + 2*GP   + (r)*20 + (c)]
#define BLs(b,r,c) dsm[(b)*4*GP + 3*GP   + (r)*20 + (c)]

__global__ void __launch_bounds__(256) gemm_3xtf32(const float* __restrict__ A,
                                                   const float* __restrict__ W,
                                                   const float* __restrict__ bias,
                                                   float* __restrict__ C,
                                                   int N, int K, int ldw, int koff,
                                                   int accumulate, int transv)
{
    extern __shared__ float dsm[];

    int t = threadIdx.x;
    int wid = t >> 5, lane = t & 31;
    int warp_m = wid >> 2;
    int warp_n = wid & 3;
    int bm = blockIdx.y * 128, bn = blockIdx.x * 128;

    float acc[4][4][4];
#pragma unroll
    for (int im = 0; im < 4; im++)
#pragma unroll
        for (int in = 0; in < 4; in++)
#pragma unroll
            for (int r = 0; r < 4; r++) acc[im][in][r] = 0.f;

    int lr = t >> 2;           // 0..63
    int lc = (t & 3) * 4;      // 0,4,8,12
    const float* Ag = A + (size_t)(bm + lr) * K + lc;
    const float* Wg = W + (size_t)(bn + lr) * ldw + koff + lc;

    float4 ra[2], rb[2];
#pragma unroll
    for (int i = 0; i < 2; i++) {
        ra[i] = *(const float4*)(Ag + (size_t)(i*64) * K);
        rb[i] = *(const float4*)(Wg + (size_t)(i*64) * ldw);
    }
    // store chunk 0 into buffer 0
#pragma unroll
    for (int i = 0; i < 2; i++) {
        int row = lr + i*64;
        float av[4] = {ra[i].x, ra[i].y, ra[i].z, ra[i].w};
        float bv[4] = {rb[i].x, rb[i].y, rb[i].z, rb[i].w};
#pragma unroll
        for (int j = 0; j < 4; j++) {
            float ah = to_tf32(av[j]); float bh = to_tf32(bv[j]);
            AHs(0,row,lc+j) = ah;  ALs(0,row,lc+j) = to_tf32(av[j] - ah);
            BHs(0,row,lc+j) = bh;  BLs(0,row,lc+j) = to_tf32(bv[j] - bh);
        }
    }
    __syncthreads();

    int nch = K / 16;
    for (int c = 0; c < nch; c++) {
        int cur = c & 1;
        bool more = (c + 1 < nch);
        if (more) {
            int kn = (c+1)*16;
#pragma unroll
            for (int i = 0; i < 2; i++) {
                ra[i] = *(const float4*)(Ag + kn + (size_t)(i*64) * K);
                rb[i] = *(const float4*)(Wg + kn + (size_t)(i*64) * ldw);
            }
        }
#pragma unroll
        for (int ks = 0; ks < 2; ks++) {
            int ak = ks*8 + (lane & 3);
            int br = warp_n*32 + (lane >> 2);
            unsigned bhf[4][2], blf[4][2];
#pragma unroll
            for (int in = 0; in < 4; in++) {
                bhf[in][0] = __float_as_uint(BHs(cur, br + in*8, ak    ));
                bhf[in][1] = __float_as_uint(BHs(cur, br + in*8, ak + 4));
                blf[in][0] = __float_as_uint(BLs(cur, br + in*8, ak    ));
                blf[in][1] = __float_as_uint(BLs(cur, br + in*8, ak + 4));
            }
#pragma unroll
            for (int im = 0; im < 4; im++) {
                int ar = warp_m*64 + im*16 + (lane >> 2);
                unsigned ah0 = __float_as_uint(AHs(cur, ar    , ak    ));
                unsigned ah1 = __float_as_uint(AHs(cur, ar + 8, ak    ));
                unsigned ah2 = __float_as_uint(AHs(cur, ar    , ak + 4));
                unsigned ah3 = __float_as_uint(AHs(cur, ar + 8, ak + 4));
                unsigned al0 = __float_as_uint(ALs(cur, ar    , ak    ));
                unsigned al1 = __float_as_uint(ALs(cur, ar + 8, ak    ));
                unsigned al2 = __float_as_uint(ALs(cur, ar    , ak + 4));
                unsigned al3 = __float_as_uint(ALs(cur, ar + 8, ak + 4));
#pragma unroll
                for (int in = 0; in < 4; in++) {
                    mma_tf32(acc[im][in], ah0, ah1, ah2, ah3, bhf[in][0], bhf[in][1]);
                    mma_tf32(acc[im][in], ah0, ah1, ah2, ah3, blf[in][0], blf[in][1]);
                    mma_tf32(acc[im][in], al0, al1, al2, al3, bhf[in][0], bhf[in][1]);
                }
            }
        }
        if (more) {
            int nxt = cur ^ 1;
#pragma unroll
            for (int i = 0; i < 2; i++) {
                int row = lr + i*64;
                float av[4] = {ra[i].x, ra[i].y, ra[i].z, ra[i].w};
                float bv[4] = {rb[i].x, rb[i].y, rb[i].z, rb[i].w};
#pragma unroll
                for (int j = 0; j < 4; j++) {
                    float ah = to_tf32(av[j]); float bh = to_tf32(bv[j]);
                    AHs(nxt,row,lc+j) = ah;  ALs(nxt,row,lc+j) = to_tf32(av[j] - ah);
                    BHs(nxt,row,lc+j) = bh;  BLs(nxt,row,lc+j) = to_tf32(bv[j] - bh);
                }
            }
        }
        __syncthreads();
    }

    // epilogue
#pragma unroll
    for (int im = 0; im < 4; im++) {
        int r0 = bm + warp_m*64 + im*16 + (lane >> 2);
#pragma unroll
        for (int in = 0; in < 4; in++) {
            int c0 = bn + warp_n*32 + in*8 + 2*(lane & 3);
            if (transv) {
                // write transposed: [b][h][d][s]
#pragma unroll
                for (int half = 0; half < 2; half++) {
                    int m = r0 + half*8;
                    float v0 = half ? acc[im][in][2] : acc[im][in][0];
                    float v1 = half ? acc[im][in][3] : acc[im][in][1];
                    float b0v = bias ? bias[c0]   : 0.f;
                    float b1v = bias ? bias[c0+1] : 0.f;
                    size_t i0 = ((size_t)((m>>10)*HH + (c0>>6))*HD + (c0&63))*SS + (m&1023);
                    size_t i1 = ((size_t)((m>>10)*HH + ((c0+1)>>6))*HD + ((c0+1)&63))*SS + (m&1023);
                    C[i0] = v0 + b0v;
                    C[i1] = v1 + b1v;
                }
            } else {
                float* C0 = C + (size_t)r0 * N + c0;
                float* C1 = C + (size_t)(r0+8) * N + c0;
                if (accumulate) {
                    C0[0] += acc[im][in][0]; C0[1] += acc[im][in][1];
                    C1[0] += acc[im][in][2]; C1[1] += acc[im][in][3];
                } else {
                    float b0v = bias ? bias[c0]   : 0.f;
                    float b1v = bias ? bias[c0+1] : 0.f;
                    C0[0] = acc[im][in][0] + b0v; C0[1] = acc[im][in][1] + b1v;
                    C1[0] = acc[im][in][2] + b0v; C1[1] = acc[im][in][3] + b1v;
                }
            }
        }
    }
}

// ---------------- Global causal attention with tensor cores ----------------
// Q tile 64, K tile 64. S^T = K @ Q^T (both natural layouts), softmax
// transposes S^T -> P, then O = P @ V with V pre-transposed ([d][s] in g_v).
// 3xTF32 everywhere. 256 threads = 8 warps.
#define ATT_SMEM_BYTES (30528*4)
__global__ void __launch_bounds__(256) attn_global_mma()
{
    extern __shared__ float sm[];
    float* QH = sm;               // [64][68]
    float* QL = QH + 4352;
    float* KH = QL + 4352;        // K tile, later V tile [d][key]
    float* KL = KH + 4352;
    float* STm = KL + 4352;       // [key 64][q 64] stride 66
    float* PH = STm + 4224;       // [q 64][key 64] stride 68
    float* PL = PH + 4352;
    float* m_s = PL + 4352;       // [64]
    float* l_s = m_s + 64;
    float* al_s = l_s + 64;

    int qt = 15 - (int)blockIdx.x;          // descending work for tail balance
    int bh = blockIdx.y;
    int b = bh >> 4, h = bh & 15;
    int t = threadIdx.x;
    int lane = t & 31, wid = t >> 5;
    int tx = t & 15, ty = t >> 4;
    int warp_m = wid & 3, warp_n = wid >> 2;
    int q0 = qt * 64;
    size_t baseQ = (size_t)b * SS * DD + h * HD;
    size_t baseVT = ((size_t)(b*HH + h)) * HD * SS;

    // load Q tile (rows q, cols d)
#pragma unroll
    for (int i = 0; i < 4; i++) {
        int r = ty + 16*i;
        float4 v = *(const float4*)(g_q + baseQ + (size_t)(q0 + r) * DD + 4*tx);
        float av[4] = {v.x, v.y, v.z, v.w};
#pragma unroll
        for (int j = 0; j < 4; j++) {
            float hi = to_tf32(av[j]);
            QH[r*68 + 4*tx + j] = hi;
            QL[r*68 + 4*tx + j] = to_tf32(av[j] - hi);
        }
    }
    if (t < 64) { m_s[t] = -3.0e38f; l_s[t] = 0.f; }

    float oacc[4][4];
#pragma unroll
    for (int nn = 0; nn < 4; nn++)
#pragma unroll
        for (int r = 0; r < 4; r++) oacc[nn][r] = 0.f;

    __syncthreads();

    for (int kt = 0; kt <= qt; kt++) {
        int k0 = kt * 64;
        // 1) load K tile [key][d]
#pragma unroll
        for (int i = 0; i < 4; i++) {
            int r = ty + 16*i;
            float4 v = *(const float4*)(g_k + baseQ + (size_t)(k0 + r) * DD + 4*tx);
            float av[4] = {v.x, v.y, v.z, v.w};
#pragma unroll
            for (int j = 0; j < 4; j++) {
                float hi = to_tf32(av[j]);
                KH[r*68 + 4*tx + j] = hi;
                KL[r*68 + 4*tx + j] = to_tf32(av[j] - hi);
            }
        }
        __syncthreads();

        // 2) S^T = K @ Q^T : m=key (warp_m), n=q (warp_n half, 4 n8 tiles)
        {
            float c4[4][4];
#pragma unroll
            for (int nn = 0; nn < 4; nn++)
#pragma unroll
                for (int r = 0; r < 4; r++) c4[nn][r] = 0.f;
#pragma unroll
            for (int kc = 0; kc < 8; kc++) {
                int ak = kc*8 + (lane & 3);
                int ar = warp_m*16 + (lane >> 2);
                unsigned ah0 = __float_as_uint(KH[ ar   *68 + ak    ]);
                unsigned ah1 = __float_as_uint(KH[(ar+8)*68 + ak    ]);
                unsigned ah2 = __float_as_uint(KH[ ar   *68 + ak + 4]);
                unsigned ah3 = __float_as_uint(KH[(ar+8)*68 + ak + 4]);
                unsigned al0 = __float_as_uint(KL[ ar   *68 + ak    ]);
                unsigned al1 = __float_as_uint(KL[(ar+8)*68 + ak    ]);
                unsigned al2 = __float_as_uint(KL[ ar   *68 + ak + 4]);
                unsigned al3 = __float_as_uint(KL[(ar+8)*68 + ak + 4]);
#pragma unroll
                for (int nn = 0; nn < 4; nn++) {
                    int br = warp_n*32 + nn*8 + (lane >> 2);
                    unsigned bh0 = __float_as_uint(QH[br*68 + ak    ]);
                    unsigned bh1 = __float_as_uint(QH[br*68 + ak + 4]);
                    unsigned bl0 = __float_as_uint(QL[br*68 + ak    ]);
                    unsigned bl1 = __float_as_uint(QL[br*68 + ak + 4]);
                    mma_tf32(c4[nn], ah0, ah1, ah2, ah3, bh0, bh1);
                    mma_tf32(c4[nn], ah0, ah1, ah2, ah3, bl0, bl1);
                    mma_tf32(c4[nn], al0, al1, al2, al3, bh0, bh1);
                }
            }
            int krow = warp_m*16 + (lane >> 2);
#pragma unroll
            for (int nn = 0; nn < 4; nn++) {
                int qc = warp_n*32 + nn*8 + 2*(lane & 3);
                STm[ krow   *66 + qc    ] = c4[nn][0];
                STm[ krow   *66 + qc + 1] = c4[nn][1];
                STm[(krow+8)*66 + qc    ] = c4[nn][2];
                STm[(krow+8)*66 + qc + 1] = c4[nn][3];
            }
        }
        // 3) issue V tile loads ([d][key] from transposed g_v)
        float4 vreg[4];
#pragma unroll
        for (int i = 0; i < 4; i++) {
            int d = ty + 16*i;
            vreg[i] = *(const float4*)(g_v + baseVT + (size_t)d * SS + k0 + 4*tx);
        }
        __syncthreads();

        // 4) online softmax: row=q (t>>2), 4 lanes per row
        {
            int row = t >> 2, sub = t & 3;
            int qglob = q0 + row;
            float mo = m_s[row];
            float mx = mo;
            float svv[16];
#pragma unroll
            for (int j = 0; j < 16; j++) {
                int key = sub + 4*j;
                float sv = STm[key*66 + row] * 0.125f;
                if (k0 + key > qglob) sv = -1.0e30f;
                svv[j] = sv;
                mx = fmaxf(mx, sv);
            }
            mx = fmaxf(mx, __shfl_xor_sync(0xffffffffu, mx, 1));
            mx = fmaxf(mx, __shfl_xor_sync(0xffffffffu, mx, 2));
            float sum = 0.f;
#pragma unroll
            for (int j = 0; j < 16; j++) {
                int key = sub + 4*j;
                float e = __expf(svv[j] - mx);
                sum += e;
                float hi = to_tf32(e);
                PH[row*68 + key] = hi;
                PL[row*68 + key] = to_tf32(e - hi);
            }
            sum += __shfl_xor_sync(0xffffffffu, sum, 1);
            sum += __shfl_xor_sync(0xffffffffu, sum, 2);
            if (sub == 0) {
                float alpha = __expf(mo - mx);
                m_s[row] = mx;
                l_s[row] = l_s[row] * alpha + sum;
                al_s[row] = alpha;
            }
        }
        // 5) store V tile into KH/KL
#pragma unroll
        for (int i = 0; i < 4; i++) {
            int d = ty + 16*i;
            float av[4] = {vreg[i].x, vreg[i].y, vreg[i].z, vreg[i].w};
#pragma unroll
            for (int j = 0; j < 4; j++) {
                float hi = to_tf32(av[j]);
                KH[d*68 + 4*tx + j] = hi;
                KL[d*68 + 4*tx + j] = to_tf32(av[j] - hi);
            }
        }
        __syncthreads();

        // 6) O *= alpha ; O += P @ V  (m=q warp_m, n=d warp_n half)
        {
            int qr = warp_m*16 + (lane >> 2);
            float a0 = al_s[qr], a1 = al_s[qr + 8];
#pragma unroll
            for (int nn = 0; nn < 4; nn++) {
                oacc[nn][0] *= a0; oacc[nn][1] *= a0;
                oacc[nn][2] *= a1; oacc[nn][3] *= a1;
            }
#pragma unroll
            for (int kc = 0; kc < 8; kc++) {
                int ak = kc*8 + (lane & 3);
                int ar = warp_m*16 + (lane >> 2);
                unsigned ah0 = __float_as_uint(PH[ ar   *68 + ak    ]);
                unsigned ah1 = __float_as_uint(PH[(ar+8)*68 + ak    ]);
                unsigned ah2 = __float_as_uint(PH[ ar   *68 + ak + 4]);
                unsigned ah3 = __float_as_uint(PH[(ar+8)*68 + ak + 4]);
                unsigned al0 = __float_as_uint(PL[ ar   *68 + ak    ]);
                unsigned al1 = __float_as_uint(PL[(ar+8)*68 + ak    ]);
                unsigned al2 = __float_as_uint(PL[ ar   *68 + ak + 4]);
                unsigned al3 = __float_as_uint(PL[(ar+8)*68 + ak + 4]);
#pragma unroll
                for (int nn = 0; nn < 4; nn++) {
                    int br = warp_n*32 + nn*8 + (lane >> 2);
                    unsigned bh0 = __float_as_uint(KH[br*68 + ak    ]);
                    unsigned bh1 = __float_as_uint(KH[br*68 + ak + 4]);
                    unsigned bl0 = __float_as_uint(KL[br*68 + ak    ]);
                    unsigned bl1 = __float_as_uint(KL[br*68 + ak + 4]);
                    mma_tf32(oacc[nn], ah0, ah1, ah2, ah3, bh0, bh1);
                    mma_tf32(oacc[nn], ah0, ah1, ah2, ah3, bl0, bl1);
                    mma_tf32(oacc[nn], al0, al1, al2, al3, bh0, bh1);
                }
            }
        }
        __syncthreads();
    }

    // write O (normalize by l)
    {
        int qr = warp_m*16 + (lane >> 2);
        float inv0 = 1.f / l_s[qr];
        float inv1 = 1.f / l_s[qr + 8];
#pragma unroll
        for (int nn = 0; nn < 4; nn++) {
            int dc = warp_n*32 + nn*8 + 2*(lane & 3);
            size_t i0 = baseQ + (size_t)(q0 + qr) * DD + dc;
            size_t i1 = baseQ + (size_t)(q0 + qr + 8) * DD + dc;
            g_attn[i0]     = oacc[nn][0] * inv0;
            g_attn[i0 + 1] = oacc[nn][1] * inv0;
            g_attn[i1]     = oacc[nn][2] * inv1;
            g_attn[i1 + 1] = oacc[nn][3] * inv1;
        }
    }
}

// ---------------- Predictor (two-stage, parallel, deterministic) ----------
__global__ void pred_partA()
{
    int b = blockIdx.x, ch = blockIdx.y;
    int t = threadIdx.x;
#pragma unroll
    for (int c = 0; c < 4; c++) {
        int col = t + 256*c;
        float s = 0.f;
        const float* p = g_gout + ((size_t)b*SS + ch*64) * DD + col;
        for (int r = 0; r < 64; r++) s += p[(size_t)r * DD];
        g_pp[((size_t)b*16 + ch)*DD + col] = s;
    }
}

__global__ void pred_partB(const float* __restrict__ Wp, const float* __restrict__ bp)
{
    __shared__ float red[256];
    int b = blockIdx.x;
    int t = threadIdx.x;
    float part = 0.f;
#pragma unroll
    for (int c = 0; c < 4; c++) {
        int col = t + 256*c;
        float s = 0.f;
#pragma unroll
        for (int ch = 0; ch < 16; ch++)
            s += g_pp[((size_t)b*16 + ch)*DD + col];
        part += (s * (1.0f/SS)) * Wp[col];
    }
    red[t] = part; __syncthreads();
    for (int o = 128; o > 0; o >>= 1) { if (t < o) red[t] += red[t+o]; __syncthreads(); }
    if (t == 0) {
        float z = red[0] + bp[0];
        g_base[b] = 1.f / (1.f + expf(-z));
    }
}

// ---------------- Span params (mirrors Python float64 int() truncation) ----
__global__ void params_kernel()
{
    float smf = (g_base[0] + g_base[1] + g_base[2] + g_base[3]) * 0.25f;
    double sm = (double)smf;
    int win = (int)(256.0 * sm);      if (win < 1) win = 1;
    int span_len = (int)(512.0 * sm); if (span_len < 1) span_len = 1;
    int lm = 512;
    if (span_len < lm) lm = span_len;
    if (win < lm) lm = win;
    g_params.win = win;
    g_params.span_len = span_len;
    g_params.local_max = lm;
    g_params.span_mean = smf;
    g_params.temp = (float)(1.0 + 0.01 * (1.0 - sm));
}

__global__ void zero_kernel(float4* p, int n4)
{
    int i = blockIdx.x * blockDim.x + threadIdx.x;
    if (i < n4) p[i] = make_float4(0.f, 0.f, 0.f, 0.f);
}

// ---------------- Local span attention (K == V, persistent over windows) ----
__global__ void __launch_bounds__(256) attn_local_kernel()
{
    __shared__ float Qs[32][65];
    __shared__ float Ks[64][65];
    __shared__ float Ss[32][65];
    __shared__ float m_s[32], l_s[32], alpha_s[32];

    SpanParams p = g_params;
    int bh = blockIdx.x;  int b = bh >> 4, h = bh & 15;
    int qt = blockIdx.y;
    int t = threadIdx.x;
    int tx = t & 15, ty = t >> 4;
    size_t base = (size_t)b * SS * DD + h * HD;
    float sc = 0.35355339059327373f / p.temp;

    for (int w = blockIdx.z; w * p.win < SS; w += (int)gridDim.z) {
        int st = w * p.win;
        int en = st + p.win; if (en > SS) en = SS;
        int wlen = en - st;
        int ks0 = st - p.span_len + p.win; if (ks0 < 0) ks0 = 0;
        int ke = st + p.span_len; if (ke > SS) ke = SS;
        int klen = ke - ks0;
        int eff = (int)((double)wlen * (double)p.span_mean);
        if (eff > wlen) eff = wlen;
        if (eff > klen) eff = klen;
        if (eff > p.local_max) eff = p.local_max;
        int q0 = qt * 32;
        if (eff <= 0 || q0 >= eff) continue;
        int qcnt = eff - q0; if (qcnt > 32) qcnt = 32;

        {
            int col = tx * 4;
#pragma unroll
            for (int rr = 0; rr < 2; rr++) {
                int r = ty + rr*16;
                float4 qv = make_float4(0.f,0.f,0.f,0.f);
                if (r < qcnt)
                    qv = *(const float4*)(g_local + base + (size_t)(st + q0 + r) * DD + col);
                Qs[r][col+0]=qv.x; Qs[r][col+1]=qv.y; Qs[r][col+2]=qv.z; Qs[r][col+3]=qv.w;
            }
        }
        if (t < 32) { m_s[t] = -3.0e38f; l_s[t] = 0.f; }
        float accO[2][4];
#pragma unroll
        for (int i = 0; i < 2; i++)
#pragma unroll
            for (int j = 0; j < 4; j++) accO[i][j] = 0.f;
        __syncthreads();

        int nkt = (eff + 63) >> 6;
        for (int kt = 0; kt < nkt; kt++) {
            {
                int col = tx * 4;
#pragma unroll
                for (int rr = 0; rr < 4; rr++) {
                    int r = ty + rr*16;
                    float4 kv = make_float4(0.f,0.f,0.f,0.f);
                    if (kt*64 + r < eff)
                        kv = *(const float4*)(g_local + base + (size_t)(ks0 + kt*64 + r) * DD + col);
                    Ks[r][col+0]=kv.x; Ks[r][col+1]=kv.y; Ks[r][col+2]=kv.z; Ks[r][col+3]=kv.w;
                }
            }
            __syncthreads();
            float sacc[2][4];
#pragma unroll
            for (int i = 0; i < 2; i++)
#pragma unroll
                for (int j = 0; j < 4; j++) sacc[i][j] = 0.f;
#pragma unroll 8
            for (int kk = 0; kk < 64; kk++) {
                float qv0 = Qs[2*ty+0][kk];
                float qv1 = Qs[2*ty+1][kk];
#pragma unroll
                for (int j = 0; j < 4; j++) {
                    float kv = Ks[4*tx+j][kk];
                    sacc[0][j] += qv0*kv;
                    sacc[1][j] += qv1*kv;
                }
            }
#pragma unroll
            for (int i = 0; i < 2; i++) {
#pragma unroll
                for (int j = 0; j < 4; j++) {
                    float sv = sacc[i][j] * sc;
                    if (kt*64 + 4*tx + j >= eff) sv = -1.0e30f;
                    Ss[2*ty+i][4*tx+j] = sv;
                }
            }
            __syncthreads();
            {
                int row = t >> 3, sub = t & 7;
                float mo = m_s[row];
                float mx = mo;
#pragma unroll
                for (int c = sub; c < 64; c += 8) mx = fmaxf(mx, Ss[row][c]);
                mx = fmaxf(mx, __shfl_xor_sync(0xffffffffu, mx, 1));
                mx = fmaxf(mx, __shfl_xor_sync(0xffffffffu, mx, 2));
                mx = fmaxf(mx, __shfl_xor_sync(0xffffffffu, mx, 4));
                float sum = 0.f;
#pragma unroll
                for (int c = sub; c < 64; c += 8) {
                    float e = __expf(Ss[row][c] - mx);
                    Ss[row][c] = e; sum += e;
                }
                sum += __shfl_xor_sync(0xffffffffu, sum, 1);
                sum += __shfl_xor_sync(0xffffffffu, sum, 2);
                sum += __shfl_xor_sync(0xffffffffu, sum, 4);
                if (sub == 0) {
                    float alpha = __expf(mo - mx);
                    m_s[row] = mx;
                    l_s[row] = l_s[row]*alpha + sum;
                    alpha_s[row] = alpha;
                }
            }
            __syncthreads();
#pragma unroll
            for (int i = 0; i < 2; i++) {
                float al = alpha_s[2*ty+i];
#pragma unroll
                for (int j = 0; j < 4; j++) accO[i][j] *= al;
            }
#pragma unroll 4
            for (int c = 0; c < 64; c++) {
                float p0 = Ss[2*ty+0][c];
                float p1 = Ss[2*ty+1][c];
#pragma unroll
                for (int j = 0; j < 4; j++) {
                    float vv = Ks[c][4*tx+j];
                    accO[0][j] += p0*vv;
                    accO[1][j] += p1*vv;
                }
            }
            __syncthreads();
        }
#pragma unroll
        for (int i = 0; i < 2; i++) {
            int r = 2*ty + i;
            if (r < qcnt) {
                float inv = 1.f / l_s[r];
#pragma unroll
                for (int j = 0; j < 4; j++)
                    g_lout[base + (size_t)(st + q0 + r) * DD + 4*tx + j] = accO[i][j] * inv;
            }
        }
        __syncthreads();
    }
}

// ---------------- launch ----------------
extern "C" void kernel_launch(void* const* d_in, const int* in_sizes, int n_in,
                              void* d_out, int out_size)
{
    const float* x     = (const float*)d_in[0];
    const float* ln_ag = (const float*)d_in[1];
    const float* ln_ab = (const float*)d_in[2];
    const float* ln_bg = (const float*)d_in[3];
    const float* ln_bb = (const float*)d_in[4];
    const float* Wq    = (const float*)d_in[5];
    const float* bq    = (const float*)d_in[6];
    const float* Wk    = (const float*)d_in[7];
    const float* Wv    = (const float*)d_in[8];
    const float* bv    = (const float*)d_in[9];
    const float* Wo    = (const float*)d_in[10];
    const float* bo    = (const float*)d_in[11];
    const float* Wp    = (const float*)d_in[12];
    const float* bp    = (const float*)d_in[13];
    const float* Wproj = (const float*)d_in[14];
    const float* bproj = (const float*)d_in[15];
    float* out = (float*)d_out;

    void *p_local, *p_globe, *p_q, *p_k, *p_v, *p_attn, *p_gout, *p_lout;
    cudaGetSymbolAddress(&p_local, g_local);
    cudaGetSymbolAddress(&p_globe, g_globe);
    cudaGetSymbolAddress(&p_q, g_q);
    cudaGetSymbolAddress(&p_k, g_k);
    cudaGetSymbolAddress(&p_v, g_v);
    cudaGetSymbolAddress(&p_attn, g_attn);
    cudaGetSymbolAddress(&p_gout, g_gout);
    cudaGetSymbolAddress(&p_lout, g_lout);

    const int GEMM_SMEM = 2*4*GP*4;   // 81920 bytes
    cudaFuncSetAttribute(gemm_3xtf32, cudaFuncAttributeMaxDynamicSharedMemorySize, GEMM_SMEM);
    cudaFuncSetAttribute(attn_global_mma, cudaFuncAttributeMaxDynamicSharedMemorySize, ATT_SMEM_BYTES);

    // 1) LayerNorms
    ln_kernel<<<MROWS, 256>>>(x, ln_ag, ln_ab, ln_bg, ln_bb);

    // 2) Q/K/V projections (V written transposed [b][h][d][s])
    dim3 ggrid(DD/128, MROWS/128);  // (8, 32)
    gemm_3xtf32<<<ggrid, 256, GEMM_SMEM>>>((const float*)p_globe, Wq, bq,      (float*)p_q, DD, DD, DD, 0, 0, 0);
    gemm_3xtf32<<<ggrid, 256, GEMM_SMEM>>>((const float*)p_globe, Wk, nullptr, (float*)p_k, DD, DD, DD, 0, 0, 0);
    gemm_3xtf32<<<ggrid, 256, GEMM_SMEM>>>((const float*)p_globe, Wv, bv,      (float*)p_v, DD, DD, DD, 0, 0, 1);

    // 3) Global causal attention (tensor cores)
    attn_global_mma<<<dim3(16, BB*HH), 256, ATT_SMEM_BYTES>>>();

    // 4) Output projection
    gemm_3xtf32<<<ggrid, 256, GEMM_SMEM>>>((const float*)p_attn, Wo, bo, (float*)p_gout, DD, DD, DD, 0, 0, 0);

    // 5) Span predictor + params
    pred_partA<<<dim3(BB, 16), 256>>>();
    pred_partB<<<BB, 256>>>(Wp, bp);
    params_kernel<<<1, 1>>>();

    // 6) Local span attention
    zero_kernel<<<(MROWS*DD/4 + 255)/256, 256>>>((float4*)p_lout, MROWS*DD/4);
    attn_local_kernel<<<dim3(BB*HH, 8, 16), 256>>>();

    // 7) Final projection: out = [local_out, globe_out] @ Wproj^T + bproj
    gemm_3xtf32<<<ggrid, 256, GEMM_SMEM>>>((const float*)p_lout, Wproj, bproj,  out, DD, DD, 2*DD, 0,  0, 0);
    gemm_3xtf32<<<ggrid, 256, GEMM_SMEM>>>((const float*)p_gout, Wproj, nullptr, out, DD, DD, 2*DD, DD, 1, 0);
}

// round 5
// speedup vs baseline: 2.4447x; 1.4332x over previous
#include <cuda_runtime.h>
#include <cuda_bf16.h>
#include <math.h>

#define BB 4
#define SS 1024
#define DD 1024
#define HH 16
#define HD 64
#define MROWS (BB*SS)

// ---------------- scratch (device globals; no allocation) ----------------
__device__ float g_local[MROWS*DD];
__device__ float g_globe[MROWS*DD];
__device__ float g_q[MROWS*DD];
__device__ float g_k[MROWS*DD];
__device__ float g_v[MROWS*DD];      // stored TRANSPOSED: [b][h][d][s]
__device__ float g_attn[MROWS*DD];
__device__ float g_gout[MROWS*DD];
__device__ float g_lout[MROWS*DD];
__device__ float g_base[BB];
__device__ float g_pp[BB*16*DD];     // predictor partials

struct SpanParams {
    int win, span_len, local_max;
    float span_mean, temp;
};
__device__ SpanParams g_params;

// ---------------- helpers ----------------
// split x into bf16 hi + bf16 lo (residual), pack two consecutive k into one u32
__device__ __forceinline__ void split_pack(float x0, float x1, unsigned &hi, unsigned &lo)
{
    __nv_bfloat16 h0 = __float2bfloat16(x0);
    __nv_bfloat16 h1 = __float2bfloat16(x1);
    float f0 = __bfloat162float(h0), f1 = __bfloat162float(h1);
    __nv_bfloat16 l0 = __float2bfloat16(x0 - f0);
    __nv_bfloat16 l1 = __float2bfloat16(x1 - f1);
    hi = ((unsigned)__bfloat16_as_ushort(h1) << 16) | (unsigned)__bfloat16_as_ushort(h0);
    lo = ((unsigned)__bfloat16_as_ushort(l1) << 16) | (unsigned)__bfloat16_as_ushort(l0);
}

__device__ __forceinline__ void mma_bf16(float c[4],
                                         unsigned a0, unsigned a1, unsigned a2, unsigned a3,
                                         unsigned b0, unsigned b1)
{
    asm volatile("mma.sync.aligned.m16n8k16.row.col.f32.bf16.bf16.f32 "
                 "{%0,%1,%2,%3}, {%4,%5,%6,%7}, {%8,%9}, {%0,%1,%2,%3};"
                 : "+f"(c[0]), "+f"(c[1]), "+f"(c[2]), "+f"(c[3])
                 : "r"(a0), "r"(a1), "r"(a2), "r"(a3), "r"(b0), "r"(b1));
}

// ---------------- LayerNorm (writes both local and globe) ----------------
__global__ void ln_kernel(const float* __restrict__ x,
                          const float* __restrict__ ga, const float* __restrict__ ba,
                          const float* __restrict__ gb, const float* __restrict__ bb)
{
    __shared__ float red[256];
    int row = blockIdx.x;
    int t = threadIdx.x;
    const float* xr = x + (size_t)row * DD;
    float v[4];
    float s = 0.f;
#pragma unroll
    for (int k = 0; k < 4; k++) { v[k] = xr[t + 256*k]; s += v[k]; }
    red[t] = s; __syncthreads();
    for (int o = 128; o > 0; o >>= 1) { if (t < o) red[t] += red[t+o]; __syncthreads(); }
    float mean = red[0] * (1.0f/DD);
    __syncthreads();
    float s2 = 0.f;
#pragma unroll
    for (int k = 0; k < 4; k++) { float d0 = v[k]-mean; s2 += d0*d0; }
    red[t] = s2; __syncthreads();
    for (int o = 128; o > 0; o >>= 1) { if (t < o) red[t] += red[t+o]; __syncthreads(); }
    float rs = rsqrtf(red[0]*(1.0f/DD) + 1e-5f);
#pragma unroll
    for (int k = 0; k < 4; k++) {
        int c = t + 256*k;
        float nh = (v[k]-mean)*rs;
        g_local[(size_t)row*DD + c] = nh*ga[c] + ba[c];
        g_globe[(size_t)row*DD + c] = nh*gb[c] + bb[c];
    }
}

// ---------------- 3xBF16 tensor-core GEMM, double-buffered ----------------
// C[M,N] = A[M,K] @ W[N, koff:koff+K]^T (+bias or +=).  W row stride = ldw.
// 128x128 CTA tile, K-chunk 32 (16 u32 words), 8 warps 2(m)x4(n), warp 64x32.
// smem rows stride 20 words (conflict-free for quad access pattern).
#define GW 20
#define GPLANE (128*GW)
#define AHu(b,r,w) usm[(b)*4*GPLANE            + (r)*GW + (w)]
#define ALu(b,r,w) usm[(b)*4*GPLANE + GPLANE   + (r)*GW + (w)]
#define BHu(b,r,w) usm[(b)*4*GPLANE + 2*GPLANE + (r)*GW + (w)]
#define BLu(b,r,w) usm[(b)*4*GPLANE + 3*GPLANE + (r)*GW + (w)]
#define GEMM_SMEM_BYTES (2*4*GPLANE*4)

__global__ void __launch_bounds__(256) gemm_3xbf16(const float* __restrict__ A,
                                                   const float* __restrict__ W,
                                                   const float* __restrict__ bias,
                                                   float* __restrict__ C,
                                                   int N, int K, int ldw, int koff,
                                                   int accumulate, int transv)
{
    extern __shared__ unsigned usm[];

    int t = threadIdx.x;
    int wid = t >> 5, lane = t & 31;
    int warp_m = wid >> 2;
    int warp_n = wid & 3;
    int bm = blockIdx.y * 128, bn = blockIdx.x * 128;
    int qq = lane >> 2, rr = lane & 3;

    float acc[4][4][4];
#pragma unroll
    for (int im = 0; im < 4; im++)
#pragma unroll
        for (int in = 0; in < 4; in++)
#pragma unroll
            for (int r = 0; r < 4; r++) acc[im][in][r] = 0.f;

    int lr = t >> 2;             // 0..63
    int lc8 = (t & 3) * 8;       // 0,8,16,24
    int wb = (t & 3) * 4;        // word base
    const float* Ag = A + (size_t)(bm + lr) * K + lc8;
    const float* Wg = W + (size_t)(bn + lr) * ldw + koff + lc8;

    float4 ra[2][2], rb[2][2];
#pragma unroll
    for (int i = 0; i < 2; i++) {
        ra[i][0] = *(const float4*)(Ag + (size_t)(i*64) * K);
        ra[i][1] = *(const float4*)(Ag + (size_t)(i*64) * K + 4);
        rb[i][0] = *(const float4*)(Wg + (size_t)(i*64) * ldw);
        rb[i][1] = *(const float4*)(Wg + (size_t)(i*64) * ldw + 4);
    }
    // store chunk 0 into buffer 0
#pragma unroll
    for (int i = 0; i < 2; i++) {
        int row = lr + i*64;
        float av[8] = {ra[i][0].x, ra[i][0].y, ra[i][0].z, ra[i][0].w,
                       ra[i][1].x, ra[i][1].y, ra[i][1].z, ra[i][1].w};
        float bv[8] = {rb[i][0].x, rb[i][0].y, rb[i][0].z, rb[i][0].w,
                       rb[i][1].x, rb[i][1].y, rb[i][1].z, rb[i][1].w};
#pragma unroll
        for (int j = 0; j < 4; j++) {
            unsigned hi, lo;
            split_pack(av[2*j], av[2*j+1], hi, lo);
            AHu(0,row,wb+j) = hi;  ALu(0,row,wb+j) = lo;
            split_pack(bv[2*j], bv[2*j+1], hi, lo);
            BHu(0,row,wb+j) = hi;  BLu(0,row,wb+j) = lo;
        }
    }
    __syncthreads();

    int nch = K / 32;
    for (int c = 0; c < nch; c++) {
        int cur = c & 1;
        bool more = (c + 1 < nch);
        if (more) {
            int kn = (c+1)*32;
#pragma unroll
            for (int i = 0; i < 2; i++) {
                ra[i][0] = *(const float4*)(Ag + kn + (size_t)(i*64) * K);
                ra[i][1] = *(const float4*)(Ag + kn + (size_t)(i*64) * K + 4);
                rb[i][0] = *(const float4*)(Wg + kn + (size_t)(i*64) * ldw);
                rb[i][1] = *(const float4*)(Wg + kn + (size_t)(i*64) * ldw + 4);
            }
        }
#pragma unroll
        for (int ks = 0; ks < 2; ks++) {
            int kw = ks*8;
            unsigned bhf[4][2], blf[4][2];
#pragma unroll
            for (int in = 0; in < 4; in++) {
                int br = warp_n*32 + in*8 + qq;
                bhf[in][0] = BHu(cur, br, kw+rr);
                bhf[in][1] = BHu(cur, br, kw+4+rr);
                blf[in][0] = BLu(cur, br, kw+rr);
                blf[in][1] = BLu(cur, br, kw+4+rr);
            }
#pragma unroll
            for (int im = 0; im < 4; im++) {
                int ar = warp_m*64 + im*16 + qq;
                unsigned ah0 = AHu(cur, ar  , kw+rr);
                unsigned ah1 = AHu(cur, ar+8, kw+rr);
                unsigned ah2 = AHu(cur, ar  , kw+4+rr);
                unsigned ah3 = AHu(cur, ar+8, kw+4+rr);
                unsigned al0 = ALu(cur, ar  , kw+rr);
                unsigned al1 = ALu(cur, ar+8, kw+rr);
                unsigned al2 = ALu(cur, ar  , kw+4+rr);
                unsigned al3 = ALu(cur, ar+8, kw+4+rr);
#pragma unroll
                for (int in = 0; in < 4; in++) {
                    mma_bf16(acc[im][in], ah0, ah1, ah2, ah3, bhf[in][0], bhf[in][1]);
                    mma_bf16(acc[im][in], ah0, ah1, ah2, ah3, blf[in][0], blf[in][1]);
                    mma_bf16(acc[im][in], al0, al1, al2, al3, bhf[in][0], bhf[in][1]);
                }
            }
        }
        if (more) {
            int nxt = cur ^ 1;
#pragma unroll
            for (int i = 0; i < 2; i++) {
                int row = lr + i*64;
                float av[8] = {ra[i][0].x, ra[i][0].y, ra[i][0].z, ra[i][0].w,
                               ra[i][1].x, ra[i][1].y, ra[i][1].z, ra[i][1].w};
                float bv[8] = {rb[i][0].x, rb[i][0].y, rb[i][0].z, rb[i][0].w,
                               rb[i][1].x, rb[i][1].y, rb[i][1].z, rb[i][1].w};
#pragma unroll
                for (int j = 0; j < 4; j++) {
                    unsigned hi, lo;
                    split_pack(av[2*j], av[2*j+1], hi, lo);
                    AHu(nxt,row,wb+j) = hi;  ALu(nxt,row,wb+j) = lo;
                    split_pack(bv[2*j], bv[2*j+1], hi, lo);
                    BHu(nxt,row,wb+j) = hi;  BLu(nxt,row,wb+j) = lo;
                }
            }
        }
        __syncthreads();
    }

    // epilogue
#pragma unroll
    for (int im = 0; im < 4; im++) {
        int r0 = bm + warp_m*64 + im*16 + qq;
#pragma unroll
        for (int in = 0; in < 4; in++) {
            int c0 = bn + warp_n*32 + in*8 + 2*rr;
            if (transv) {
#pragma unroll
                for (int half = 0; half < 2; half++) {
                    int m = r0 + half*8;
                    float v0 = half ? acc[im][in][2] : acc[im][in][0];
                    float v1 = half ? acc[im][in][3] : acc[im][in][1];
                    float b0v = bias ? bias[c0]   : 0.f;
                    float b1v = bias ? bias[c0+1] : 0.f;
                    size_t i0 = ((size_t)((m>>10)*HH + (c0>>6))*HD + (c0&63))*SS + (m&1023);
                    size_t i1 = ((size_t)((m>>10)*HH + ((c0+1)>>6))*HD + ((c0+1)&63))*SS + (m&1023);
                    C[i0] = v0 + b0v;
                    C[i1] = v1 + b1v;
                }
            } else {
                float* C0 = C + (size_t)r0 * N + c0;
                float* C1 = C + (size_t)(r0+8) * N + c0;
                if (accumulate) {
                    C0[0] += acc[im][in][0]; C0[1] += acc[im][in][1];
                    C1[0] += acc[im][in][2]; C1[1] += acc[im][in][3];
                } else {
                    float b0v = bias ? bias[c0]   : 0.f;
                    float b1v = bias ? bias[c0+1] : 0.f;
                    C0[0] = acc[im][in][0] + b0v; C0[1] = acc[im][in][1] + b1v;
                    C1[0] = acc[im][in][2] + b0v; C1[1] = acc[im][in][3] + b1v;
                }
            }
        }
    }
}

// ---------------- Global causal attention with bf16x3 tensor cores --------
// Q tile 64, K tile 64. S^T = K @ Q^T, softmax transposes S^T -> P (bf16x2
// packed pairs), O = P @ V (V pre-transposed [d][s]). 256 threads = 8 warps.
// u32 word planes stride 36 (conflict-free).
#define AW 36
#define A_QH 0
#define A_QL 2304
#define A_KH 4608
#define A_KL 6912
#define A_PH 9216
#define A_PL 11520
#define A_ST 13824               // float [64][66]
#define A_MS (13824 + 4224)
#define ATT_SMEM_WORDS (13824 + 4224 + 192)
#define ATT_SMEM_BYTES (ATT_SMEM_WORDS*4)

__global__ void __launch_bounds__(256) attn_global_mma()
{
    extern __shared__ unsigned usm[];
    float* STm = (float*)(usm + A_ST);
    float* m_s = (float*)(usm + A_MS);
    float* l_s = m_s + 64;
    float* al_s = l_s + 64;

    int qt = 15 - (int)blockIdx.x;
    int bh = blockIdx.y;
    int b = bh >> 4, h = bh & 15;
    int t = threadIdx.x;
    int lane = t & 31, wid = t >> 5;
    int tx = t & 15, ty = t >> 4;
    int warp_m = wid & 3, warp_n = wid >> 2;
    int qq = lane >> 2, rr = lane & 3;
    int q0 = qt * 64;
    size_t baseQ = (size_t)b * SS * DD + h * HD;
    size_t baseVT = ((size_t)(b*HH + h)) * HD * SS;

    // load Q tile (rows q, cols d) -> QH/QL word planes
#pragma unroll
    for (int i = 0; i < 4; i++) {
        int r = ty + 16*i;
        float4 v = *(const float4*)(g_q + baseQ + (size_t)(q0 + r) * DD + 4*tx);
        unsigned h0, l0, h1, l1;
        split_pack(v.x, v.y, h0, l0);
        split_pack(v.z, v.w, h1, l1);
        usm[A_QH + r*AW + 2*tx    ] = h0;  usm[A_QL + r*AW + 2*tx    ] = l0;
        usm[A_QH + r*AW + 2*tx + 1] = h1;  usm[A_QL + r*AW + 2*tx + 1] = l1;
    }
    if (t < 64) { m_s[t] = -3.0e38f; l_s[t] = 0.f; }

    float oacc[4][4];
#pragma unroll
    for (int nn = 0; nn < 4; nn++)
#pragma unroll
        for (int r = 0; r < 4; r++) oacc[nn][r] = 0.f;

    __syncthreads();

    for (int kt = 0; kt <= qt; kt++) {
        int k0 = kt * 64;
        // 1) load K tile [key][d words]
#pragma unroll
        for (int i = 0; i < 4; i++) {
            int r = ty + 16*i;
            float4 v = *(const float4*)(g_k + baseQ + (size_t)(k0 + r) * DD + 4*tx);
            unsigned h0, l0, h1, l1;
            split_pack(v.x, v.y, h0, l0);
            split_pack(v.z, v.w, h1, l1);
            usm[A_KH + r*AW + 2*tx    ] = h0;  usm[A_KL + r*AW + 2*tx    ] = l0;
            usm[A_KH + r*AW + 2*tx + 1] = h1;  usm[A_KL + r*AW + 2*tx + 1] = l1;
        }
        __syncthreads();

        // 2) S^T = K @ Q^T : m=key (warp_m 16-tile), n=q (warp_n half)
        {
            float c4[4][4];
#pragma unroll
            for (int nn = 0; nn < 4; nn++)
#pragma unroll
                for (int r = 0; r < 4; r++) c4[nn][r] = 0.f;
#pragma unroll
            for (int ks = 0; ks < 4; ks++) {
                int kw = ks*8;
                int ar = warp_m*16 + qq;
                unsigned ah0 = usm[A_KH +  ar   *AW + kw+rr];
                unsigned ah1 = usm[A_KH + (ar+8)*AW + kw+rr];
                unsigned ah2 = usm[A_KH +  ar   *AW + kw+4+rr];
                unsigned ah3 = usm[A_KH + (ar+8)*AW + kw+4+rr];
                unsigned al0 = usm[A_KL +  ar   *AW + kw+rr];
                unsigned al1 = usm[A_KL + (ar+8)*AW + kw+rr];
                unsigned al2 = usm[A_KL +  ar   *AW + kw+4+rr];
                unsigned al3 = usm[A_KL + (ar+8)*AW + kw+4+rr];
#pragma unroll
                for (int nn = 0; nn < 4; nn++) {
                    int br = warp_n*32 + nn*8 + qq;
                    unsigned bh0 = usm[A_QH + br*AW + kw+rr];
                    unsigned bh1 = usm[A_QH + br*AW + kw+4+rr];
                    unsigned bl0 = usm[A_QL + br*AW + kw+rr];
                    unsigned bl1 = usm[A_QL + br*AW + kw+4+rr];
                    mma_bf16(c4[nn], ah0, ah1, ah2, ah3, bh0, bh1);
                    mma_bf16(c4[nn], ah0, ah1, ah2, ah3, bl0, bl1);
                    mma_bf16(c4[nn], al0, al1, al2, al3, bh0, bh1);
                }
            }
            int krow = warp_m*16 + qq;
#pragma unroll
            for (int nn = 0; nn < 4; nn++) {
                int qc = warp_n*32 + nn*8 + 2*rr;
                STm[ krow   *66 + qc    ] = c4[nn][0];
                STm[ krow   *66 + qc + 1] = c4[nn][1];
                STm[(krow+8)*66 + qc    ] = c4[nn][2];
                STm[(krow+8)*66 + qc + 1] = c4[nn][3];
            }
        }
        // 3) issue V tile loads ([d][key] from transposed g_v)
        float4 vreg[4];
#pragma unroll
        for (int i = 0; i < 4; i++) {
            int d = ty + 16*i;
            vreg[i] = *(const float4*)(g_v + baseVT + (size_t)d * SS + k0 + 4*tx);
        }
        __syncthreads();

        // 4) online softmax: row=q (t>>2), 4 lanes per row, 16 contiguous keys each
        {
            int row = t >> 2, sub = t & 3;
            int qglob = q0 + row;
            float mo = m_s[row];
            float mx = mo;
            float ev[16];
#pragma unroll
            for (int j = 0; j < 16; j++) {
                int key = sub*16 + j;
                float sv = STm[key*66 + row] * 0.125f;
                if (k0 + key > qglob) sv = -1.0e30f;
                ev[j] = sv;
                mx = fmaxf(mx, sv);
            }
            mx = fmaxf(mx, __shfl_xor_sync(0xffffffffu, mx, 1));
            mx = fmaxf(mx, __shfl_xor_sync(0xffffffffu, mx, 2));
            float sum = 0.f;
#pragma unroll
            for (int j = 0; j < 16; j++) {
                float e = __expf(ev[j] - mx);
                ev[j] = e; sum += e;
            }
#pragma unroll
            for (int j = 0; j < 8; j++) {
                unsigned hi, lo;
                split_pack(ev[2*j], ev[2*j+1], hi, lo);
                usm[A_PH + row*AW + sub*8 + j] = hi;
                usm[A_PL + row*AW + sub*8 + j] = lo;
            }
            sum += __shfl_xor_sync(0xffffffffu, sum, 1);
            sum += __shfl_xor_sync(0xffffffffu, sum, 2);
            if (sub == 0) {
                float alpha = __expf(mo - mx);
                m_s[row] = mx;
                l_s[row] = l_s[row] * alpha + sum;
                al_s[row] = alpha;
            }
        }
        // 5) store V tile into KH/KL ([d][key words])
#pragma unroll
        for (int i = 0; i < 4; i++) {
            int d = ty + 16*i;
            unsigned h0, l0, h1, l1;
            split_pack(vreg[i].x, vreg[i].y, h0, l0);
            split_pack(vreg[i].z, vreg[i].w, h1, l1);
            usm[A_KH + d*AW + 2*tx    ] = h0;  usm[A_KL + d*AW + 2*tx    ] = l0;
            usm[A_KH + d*AW + 2*tx + 1] = h1;  usm[A_KL + d*AW + 2*tx + 1] = l1;
        }
        __syncthreads();

        // 6) O *= alpha ; O += P @ V  (m=q warp_m, n=d warp_n half)
        {
            int qr = warp_m*16 + qq;
            float a0 = al_s[qr], a1 = al_s[qr + 8];
#pragma unroll
            for (int nn = 0; nn < 4; nn++) {
                oacc[nn][0] *= a0; oacc[nn][1] *= a0;
                oacc[nn][2] *= a1; oacc[nn][3] *= a1;
            }
#pragma unroll
            for (int ks = 0; ks < 4; ks++) {
                int kw = ks*8;
                int ar = warp_m*16 + qq;
                unsigned ah0 = usm[A_PH +  ar   *AW + kw+rr];
                unsigned ah1 = usm[A_PH + (ar+8)*AW + kw+rr];
                unsigned ah2 = usm[A_PH +  ar   *AW + kw+4+rr];
                unsigned ah3 = usm[A_PH + (ar+8)*AW + kw+4+rr];
                unsigned al0 = usm[A_PL +  ar   *AW + kw+rr];
                unsigned al1 = usm[A_PL + (ar+8)*AW + kw+rr];
                unsigned al2 = usm[A_PL +  ar   *AW + kw+4+rr];
                unsigned al3 = usm[A_PL + (ar+8)*AW + kw+4+rr];
#pragma unroll
                for (int nn = 0; nn < 4; nn++) {
                    int br = warp_n*32 + nn*8 + qq;
                    unsigned bh0 = usm[A_KH + br*AW + kw+rr];
                    unsigned bh1 = usm[A_KH + br*AW + kw+4+rr];
                    unsigned bl0 = usm[A_KL + br*AW + kw+rr];
                    unsigned bl1 = usm[A_KL + br*AW + kw+4+rr];
                    mma_bf16(oacc[nn], ah0, ah1, ah2, ah3, bh0, bh1);
                    mma_bf16(oacc[nn], ah0, ah1, ah2, ah3, bl0, bl1);
                    mma_bf16(oacc[nn], al0, al1, al2, al3, bh0, bh1);
                }
            }
        }
        __syncthreads();
    }

    // write O (normalize by l)
    {
        int qr = warp_m*16 + qq;
        float inv0 = 1.f / l_s[qr];
        float inv1 = 1.f / l_s[qr + 8];
#pragma unroll
        for (int nn = 0; nn < 4; nn++) {
            int dc = warp_n*32 + nn*8 + 2*rr;
            size_t i0 = baseQ + (size_t)(q0 + qr) * DD + dc;
            size_t i1 = baseQ + (size_t)(q0 + qr + 8) * DD + dc;
            g_attn[i0]     = oacc[nn][0] * inv0;
            g_attn[i0 + 1] = oacc[nn][1] * inv0;
            g_attn[i1]     = oacc[nn][2] * inv1;
            g_attn[i1 + 1] = oacc[nn][3] * inv1;
        }
    }
}

// ---------------- Predictor (two-stage, parallel, deterministic) ----------
__global__ void pred_partA()
{
    int b = blockIdx.x, ch = blockIdx.y;
    int t = threadIdx.x;
#pragma unroll
    for (int c = 0; c < 4; c++) {
        int col = t + 256*c;
        float s = 0.f;
        const float* p = g_gout + ((size_t)b*SS + ch*64) * DD + col;
        for (int r = 0; r < 64; r++) s += p[(size_t)r * DD];
        g_pp[((size_t)b*16 + ch)*DD + col] = s;
    }
}

__global__ void pred_partB(const float* __restrict__ Wp, const float* __restrict__ bp)
{
    __shared__ float red[256];
    int b = blockIdx.x;
    int t = threadIdx.x;
    float part = 0.f;
#pragma unroll
    for (int c = 0; c < 4; c++) {
        int col = t + 256*c;
        float s = 0.f;
#pragma unroll
        for (int ch = 0; ch < 16; ch++)
            s += g_pp[((size_t)b*16 + ch)*DD + col];
        part += (s * (1.0f/SS)) * Wp[col];
    }
    red[t] = part; __syncthreads();
    for (int o = 128; o > 0; o >>= 1) { if (t < o) red[t] += red[t+o]; __syncthreads(); }
    if (t == 0) {
        float z = red[0] + bp[0];
        g_base[b] = 1.f / (1.f + expf(-z));
    }
}

// ---------------- Span params (mirrors Python float64 int() truncation) ----
__global__ void params_kernel()
{
    float smf = (g_base[0] + g_base[1] + g_base[2] + g_base[3]) * 0.25f;
    double sm = (double)smf;
    int win = (int)(256.0 * sm);      if (win < 1) win = 1;
    int span_len = (int)(512.0 * sm); if (span_len < 1) span_len = 1;
    int lm = 512;
    if (span_len < lm) lm = span_len;
    if (win < lm) lm = win;
    g_params.win = win;
    g_params.span_len = span_len;
    g_params.local_max = lm;
    g_params.span_mean = smf;
    g_params.temp = (float)(1.0 + 0.01 * (1.0 - sm));
}

__global__ void zero_kernel(float4* p, int n4)
{
    int i = blockIdx.x * blockDim.x + threadIdx.x;
    if (i < n4) p[i] = make_float4(0.f, 0.f, 0.f, 0.f);
}

// ---------------- Local span attention (K == V, persistent over windows) ----
__global__ void __launch_bounds__(256) attn_local_kernel()
{
    __shared__ float Qs[32][65];
    __shared__ float Ks[64][65];
    __shared__ float Ss[32][65];
    __shared__ float m_s[32], l_s[32], alpha_s[32];

    SpanParams p = g_params;
    int bh = blockIdx.x;  int b = bh >> 4, h = bh & 15;
    int qt = blockIdx.y;
    int t = threadIdx.x;
    int tx = t & 15, ty = t >> 4;
    size_t base = (size_t)b * SS * DD + h * HD;
    float sc = 0.35355339059327373f / p.temp;

    for (int w = blockIdx.z; w * p.win < SS; w += (int)gridDim.z) {
        int st = w * p.win;
        int en = st + p.win; if (en > SS) en = SS;
        int wlen = en - st;
        int ks0 = st - p.span_len + p.win; if (ks0 < 0) ks0 = 0;
        int ke = st + p.span_len; if (ke > SS) ke = SS;
        int klen = ke - ks0;
        int eff = (int)((double)wlen * (double)p.span_mean);
        if (eff > wlen) eff = wlen;
        if (eff > klen) eff = klen;
        if (eff > p.local_max) eff = p.local_max;
        int q0 = qt * 32;
        if (eff <= 0 || q0 >= eff) continue;
        int qcnt = eff - q0; if (qcnt > 32) qcnt = 32;

        {
            int col = tx * 4;
#pragma unroll
            for (int rr = 0; rr < 2; rr++) {
                int r = ty + rr*16;
                float4 qv = make_float4(0.f,0.f,0.f,0.f);
                if (r < qcnt)
                    qv = *(const float4*)(g_local + base + (size_t)(st + q0 + r) * DD + col);
                Qs[r][col+0]=qv.x; Qs[r][col+1]=qv.y; Qs[r][col+2]=qv.z; Qs[r][col+3]=qv.w;
            }
        }
        if (t < 32) { m_s[t] = -3.0e38f; l_s[t] = 0.f; }
        float accO[2][4];
#pragma unroll
        for (int i = 0; i < 2; i++)
#pragma unroll
            for (int j = 0; j < 4; j++) accO[i][j] = 0.f;
        __syncthreads();

        int nkt = (eff + 63) >> 6;
        for (int kt = 0; kt < nkt; kt++) {
            {
                int col = tx * 4;
#pragma unroll
                for (int rr = 0; rr < 4; rr++) {
                    int r = ty + rr*16;
                    float4 kv = make_float4(0.f,0.f,0.f,0.f);
                    if (kt*64 + r < eff)
                        kv = *(const float4*)(g_local + base + (size_t)(ks0 + kt*64 + r) * DD + col);
                    Ks[r][col+0]=kv.x; Ks[r][col+1]=kv.y; Ks[r][col+2]=kv.z; Ks[r][col+3]=kv.w;
                }
            }
            __syncthreads();
            float sacc[2][4];
#pragma unroll
            for (int i = 0; i < 2; i++)
#pragma unroll
                for (int j = 0; j < 4; j++) sacc[i][j] = 0.f;
#pragma unroll 8
            for (int kk = 0; kk < 64; kk++) {
                float qv0 = Qs[2*ty+0][kk];
                float qv1 = Qs[2*ty+1][kk];
#pragma unroll
                for (int j = 0; j < 4; j++) {
                    float kv = Ks[4*tx+j][kk];
                    sacc[0][j] += qv0*kv;
                    sacc[1][j] += qv1*kv;
                }
            }
#pragma unroll
            for (int i = 0; i < 2; i++) {
#pragma unroll
                for (int j = 0; j < 4; j++) {
                    float sv = sacc[i][j] * sc;
                    if (kt*64 + 4*tx + j >= eff) sv = -1.0e30f;
                    Ss[2*ty+i][4*tx+j] = sv;
                }
            }
            __syncthreads();
            {
                int row = t >> 3, sub = t & 7;
                float mo = m_s[row];
                float mx = mo;
#pragma unroll
                for (int c = sub; c < 64; c += 8) mx = fmaxf(mx, Ss[row][c]);
                mx = fmaxf(mx, __shfl_xor_sync(0xffffffffu, mx, 1));
                mx = fmaxf(mx, __shfl_xor_sync(0xffffffffu, mx, 2));
                mx = fmaxf(mx, __shfl_xor_sync(0xffffffffu, mx, 4));
                float sum = 0.f;
#pragma unroll
                for (int c = sub; c < 64; c += 8) {
                    float e = __expf(Ss[row][c] - mx);
                    Ss[row][c] = e; sum += e;
                }
                sum += __shfl_xor_sync(0xffffffffu, sum, 1);
                sum += __shfl_xor_sync(0xffffffffu, sum, 2);
                sum += __shfl_xor_sync(0xffffffffu, sum, 4);
                if (sub == 0) {
                    float alpha = __expf(mo - mx);
                    m_s[row] = mx;
                    l_s[row] = l_s[row]*alpha + sum;
                    alpha_s[row] = alpha;
                }
            }
            __syncthreads();
#pragma unroll
            for (int i = 0; i < 2; i++) {
                float al = alpha_s[2*ty+i];
#pragma unroll
                for (int j = 0; j < 4; j++) accO[i][j] *= al;
            }
#pragma unroll 4
            for (int c = 0; c < 64; c++) {
                float p0 = Ss[2*ty+0][c];
                float p1 = Ss[2*ty+1][c];
#pragma unroll
                for (int j = 0; j < 4; j++) {
                    float vv = Ks[c][4*tx+j];
                    accO[0][j] += p0*vv;
                    accO[1][j] += p1*vv;
                }
            }
            __syncthreads();
        }
#pragma unroll
        for (int i = 0; i < 2; i++) {
            int r = 2*ty + i;
            if (r < qcnt) {
                float inv = 1.f / l_s[r];
#pragma unroll
                for (int j = 0; j < 4; j++)
                    g_lout[base + (size_t)(st + q0 + r) * DD + 4*tx + j] = accO[i][j] * inv;
            }
        }
        __syncthreads();
    }
}

// ---------------- launch ----------------
extern "C" void kernel_launch(void* const* d_in, const int* in_sizes, int n_in,
                              void* d_out, int out_size)
{
    const float* x     = (const float*)d_in[0];
    const float* ln_ag = (const float*)d_in[1];
    const float* ln_ab = (const float*)d_in[2];
    const float* ln_bg = (const float*)d_in[3];
    const float* ln_bb = (const float*)d_in[4];
    const float* Wq    = (const float*)d_in[5];
    const float* bq    = (const float*)d_in[6];
    const float* Wk    = (const float*)d_in[7];
    const float* Wv    = (const float*)d_in[8];
    const float* bv    = (const float*)d_in[9];
    const float* Wo    = (const float*)d_in[10];
    const float* bo    = (const float*)d_in[11];
    const float* Wp    = (const float*)d_in[12];
    const float* bp    = (const float*)d_in[13];
    const float* Wproj = (const float*)d_in[14];
    const float* bproj = (const float*)d_in[15];
    float* out = (float*)d_out;

    void *p_local, *p_globe, *p_q, *p_k, *p_v, *p_attn, *p_gout, *p_lout;
    cudaGetSymbolAddress(&p_local, g_local);
    cudaGetSymbolAddress(&p_globe, g_globe);
    cudaGetSymbolAddress(&p_q, g_q);
    cudaGetSymbolAddress(&p_k, g_k);
    cudaGetSymbolAddress(&p_v, g_v);
    cudaGetSymbolAddress(&p_attn, g_attn);
    cudaGetSymbolAddress(&p_gout, g_gout);
    cudaGetSymbolAddress(&p_lout, g_lout);

    cudaFuncSetAttribute(gemm_3xbf16, cudaFuncAttributeMaxDynamicSharedMemorySize, GEMM_SMEM_BYTES);
    cudaFuncSetAttribute(attn_global_mma, cudaFuncAttributeMaxDynamicSharedMemorySize, ATT_SMEM_BYTES);

    // 1) LayerNorms
    ln_kernel<<<MROWS, 256>>>(x, ln_ag, ln_ab, ln_bg, ln_bb);

    // 2) Q/K/V projections (V written transposed [b][h][d][s])
    dim3 ggrid(DD/128, MROWS/128);  // (8, 32)
    gemm_3xbf16<<<ggrid, 256, GEMM_SMEM_BYTES>>>((const float*)p_globe, Wq, bq,      (float*)p_q, DD, DD, DD, 0, 0, 0);
    gemm_3xbf16<<<ggrid, 256, GEMM_SMEM_BYTES>>>((const float*)p_globe, Wk, nullptr, (float*)p_k, DD, DD, DD, 0, 0, 0);
    gemm_3xbf16<<<ggrid, 256, GEMM_SMEM_BYTES>>>((const float*)p_globe, Wv, bv,      (float*)p_v, DD, DD, DD, 0, 0, 1);

    // 3) Global causal attention (bf16x3 tensor cores)
    attn_global_mma<<<dim3(16, BB*HH), 256, ATT_SMEM_BYTES>>>();

    // 4) Output projection
    gemm_3xbf16<<<ggrid, 256, GEMM_SMEM_BYTES>>>((const float*)p_attn, Wo, bo, (float*)p_gout, DD, DD, DD, 0, 0, 0);

    // 5) Span predictor + params
    pred_partA<<<dim3(BB, 16), 256>>>();
    pred_partB<<<BB, 256>>>(Wp, bp);
    params_kernel<<<1, 1>>>();

    // 6) Local span attention
    zero_kernel<<<(MROWS*DD/4 + 255)/256, 256>>>((float4*)p_lout, MROWS*DD/4);
    attn_local_kernel<<<dim3(BB*HH, 8, 16), 256>>>();

    // 7) Final projection: out = [local_out, globe_out] @ Wproj^T + bproj
    gemm_3xbf16<<<ggrid, 256, GEMM_SMEM_BYTES>>>((const float*)p_lout, Wproj, bproj,  out, DD, DD, 2*DD, 0,  0, 0);
    gemm_3xbf16<<<ggrid, 256, GEMM_SMEM_BYTES>>>((const float*)p_gout, Wproj, nullptr, out, DD, DD, 2*DD, DD, 1, 0);
}

// round 6
// speedup vs baseline: 2.8697x; 1.1739x over previous
#include <cuda_runtime.h>
#include <cuda_bf16.h>
#include <math.h>

#define BB 4
#define SS 1024
#define DD 1024
#define HH 16
#define HD 64
#define MROWS (BB*SS)

// ---------------- scratch (device globals; no allocation) ----------------
__device__ float g_local[MROWS*DD];
__device__ float g_gout[MROWS*DD];
__device__ float g_base[BB];
__device__ float g_pp[BB*16*DD];

// bf16 hi/lo planes
__device__ __nv_bfloat16 gb_globe_h[MROWS*DD], gb_globe_l[MROWS*DD];
__device__ __nv_bfloat16 gb_q_h[MROWS*DD],    gb_q_l[MROWS*DD];
__device__ __nv_bfloat16 gb_k_h[MROWS*DD],    gb_k_l[MROWS*DD];
__device__ __nv_bfloat16 gb_v_h[MROWS*DD],    gb_v_l[MROWS*DD];   // transposed [b][h][d][s]
__device__ __nv_bfloat16 gb_attn_h[MROWS*DD], gb_attn_l[MROWS*DD];
__device__ __nv_bfloat16 gb_gout_h[MROWS*DD], gb_gout_l[MROWS*DD];
__device__ __nv_bfloat16 gb_lout_h[MROWS*DD], gb_lout_l[MROWS*DD];
__device__ __nv_bfloat16 gb_wq_h[DD*DD], gb_wq_l[DD*DD];
__device__ __nv_bfloat16 gb_wk_h[DD*DD], gb_wk_l[DD*DD];
__device__ __nv_bfloat16 gb_wv_h[DD*DD], gb_wv_l[DD*DD];
__device__ __nv_bfloat16 gb_wo_h[DD*DD], gb_wo_l[DD*DD];
__device__ __nv_bfloat16 gb_wp_h[DD*2*DD], gb_wp_l[DD*2*DD];

struct SpanParams {
    int win, span_len, local_max;
    float span_mean, temp;
};
__device__ SpanParams g_params;

// ---------------- helpers ----------------
__device__ __forceinline__ void split_pack(float x0, float x1, unsigned &hi, unsigned &lo)
{
    __nv_bfloat16 h0 = __float2bfloat16(x0);
    __nv_bfloat16 h1 = __float2bfloat16(x1);
    float f0 = __bfloat162float(h0), f1 = __bfloat162float(h1);
    __nv_bfloat16 l0 = __float2bfloat16(x0 - f0);
    __nv_bfloat16 l1 = __float2bfloat16(x1 - f1);
    hi = ((unsigned)__bfloat16_as_ushort(h1) << 16) | (unsigned)__bfloat16_as_ushort(h0);
    lo = ((unsigned)__bfloat16_as_ushort(l1) << 16) | (unsigned)__bfloat16_as_ushort(l0);
}

__device__ __forceinline__ void split_store(float v, __nv_bfloat16* hi, __nv_bfloat16* lo, size_t idx)
{
    __nv_bfloat16 h = __float2bfloat16(v);
    hi[idx] = h;
    lo[idx] = __float2bfloat16(v - __bfloat162float(h));
}

__device__ __forceinline__ void mma_bf16(float c[4],
                                         unsigned a0, unsigned a1, unsigned a2, unsigned a3,
                                         unsigned b0, unsigned b1)
{
    asm volatile("mma.sync.aligned.m16n8k16.row.col.f32.bf16.bf16.f32 "
                 "{%0,%1,%2,%3}, {%4,%5,%6,%7}, {%8,%9}, {%0,%1,%2,%3};"
                 : "+f"(c[0]), "+f"(c[1]), "+f"(c[2]), "+f"(c[3])
                 : "r"(a0), "r"(a1), "r"(a2), "r"(a3), "r"(b0), "r"(b1));
}

__device__ __forceinline__ void ldsm4(unsigned &r0, unsigned &r1, unsigned &r2, unsigned &r3, unsigned addr)
{
    asm volatile("ldmatrix.sync.aligned.m8n8.x4.shared.b16 {%0,%1,%2,%3}, [%4];"
                 : "=r"(r0), "=r"(r1), "=r"(r2), "=r"(r3) : "r"(addr));
}

__device__ __forceinline__ void cpa16(unsigned saddr, const void* g)
{
    asm volatile("cp.async.ca.shared.global [%0], [%1], 16;" :: "r"(saddr), "l"(g));
}

// ---------------- weight split ----------------
__global__ void conv_split(const float4* __restrict__ src,
                           __nv_bfloat16* __restrict__ hi,
                           __nv_bfloat16* __restrict__ lo, int n4)
{
    int i = blockIdx.x * blockDim.x + threadIdx.x;
    if (i >= n4) return;
    float4 v = src[i];
    unsigned h0, l0, h1, l1;
    split_pack(v.x, v.y, h0, l0);
    split_pack(v.z, v.w, h1, l1);
    uint2* ph = (uint2*)(hi + (size_t)i*4);
    uint2* pl = (uint2*)(lo + (size_t)i*4);
    *ph = make_uint2(h0, h1);
    *pl = make_uint2(l0, l1);
}

__global__ void zero_u4(uint4* p, int n)
{
    int i = blockIdx.x * blockDim.x + threadIdx.x;
    if (i < n) p[i] = make_uint4(0u,0u,0u,0u);
}

// ---------------- LayerNorm: fp32 local + bf16 hi/lo globe ----------------
__global__ void ln_kernel(const float* __restrict__ x,
                          const float* __restrict__ ga, const float* __restrict__ ba,
                          const float* __restrict__ gb, const float* __restrict__ bb)
{
    __shared__ float red[256];
    int row = blockIdx.x;
    int t = threadIdx.x;
    const float* xr = x + (size_t)row * DD;
    float v[4];
    float s = 0.f;
#pragma unroll
    for (int k = 0; k < 4; k++) { v[k] = xr[t + 256*k]; s += v[k]; }
    red[t] = s; __syncthreads();
    for (int o = 128; o > 0; o >>= 1) { if (t < o) red[t] += red[t+o]; __syncthreads(); }
    float mean = red[0] * (1.0f/DD);
    __syncthreads();
    float s2 = 0.f;
#pragma unroll
    for (int k = 0; k < 4; k++) { float d0 = v[k]-mean; s2 += d0*d0; }
    red[t] = s2; __syncthreads();
    for (int o = 128; o > 0; o >>= 1) { if (t < o) red[t] += red[t+o]; __syncthreads(); }
    float rs = rsqrtf(red[0]*(1.0f/DD) + 1e-5f);
#pragma unroll
    for (int k = 0; k < 4; k++) {
        int c = t + 256*k;
        float nh = (v[k]-mean)*rs;
        size_t idx = (size_t)row*DD + c;
        g_local[idx] = nh*ga[c] + ba[c];
        split_store(nh*gb[c] + bb[c], gb_globe_h, gb_globe_l, idx);
    }
}

// ---------------- bf16x3 GEMM: cp.async + ldmatrix, double-buffered -------
// C[M,N] = (Ah+Al)[M,K] @ (Wh+Wl)[N, koff:koff+K]^T, drop lo*lo.
// 128x128 CTA, K-chunk 32, 8 warps 2(m)x4(n). smem row stride 80B (pad 16B).
#define GSM_ROWB 80
#define GSM_PLANE 10240
#define GSM_BUF 40960
#define GEMM_SMEM_BYTES (2*GSM_BUF)

__global__ void __launch_bounds__(256, 2) gemm_bf16lm(
    const __nv_bfloat16* __restrict__ Ah, const __nv_bfloat16* __restrict__ Al,
    const __nv_bfloat16* __restrict__ Wh, const __nv_bfloat16* __restrict__ Wl,
    const float* __restrict__ bias, float* __restrict__ C,
    __nv_bfloat16* __restrict__ Chi, __nv_bfloat16* __restrict__ Clo,
    int N, int K, int ldw, int koff, int accumulate, int transv)
{
    extern __shared__ char sm8[];
    unsigned sbase = (unsigned)__cvta_generic_to_shared(sm8);

    int t = threadIdx.x;
    int wid = t >> 5, lane = t & 31;
    int warp_m = wid >> 2, warp_n = wid & 3;
    int bm = blockIdx.y * 128, bn = blockIdx.x * 128;
    int qq = lane >> 2, rr = lane & 3;

    // cp.async source layout: thread -> (row = t>>1, 32B span = (t&1)*32B)
    int crow = t >> 1;
    int csp = t & 1;
    const __nv_bfloat16* gAh = Ah + (size_t)(bm + crow) * K + csp*16;
    const __nv_bfloat16* gAl = Al + (size_t)(bm + crow) * K + csp*16;
    const __nv_bfloat16* gWh = Wh + (size_t)(bn + crow) * ldw + koff + csp*16;
    const __nv_bfloat16* gWl = Wl + (size_t)(bn + crow) * ldw + koff + csp*16;
    unsigned dOff = crow*GSM_ROWB + csp*32;

    // ldmatrix lane addressing (A: m-major frag; B: n-major frag)
    int mq = lane >> 3, j = lane & 7;
    unsigned aoff = (warp_m*64 + (mq&1)*8 + j)*GSM_ROWB + (mq>>1)*16;
    unsigned boff = (warp_n*32 + (mq>>1)*8 + j)*GSM_ROWB + (mq&1)*16;

    float acc[4][4][4];
#pragma unroll
    for (int im = 0; im < 4; im++)
#pragma unroll
        for (int in = 0; in < 4; in++)
#pragma unroll
            for (int r = 0; r < 4; r++) acc[im][in][r] = 0.f;

#define ISSUE(buf, kc) do { \
    unsigned d = sbase + (buf)*GSM_BUF + dOff; \
    cpa16(d,                   gAh + (kc)*32); \
    cpa16(d+16,                gAh + (kc)*32 + 8); \
    cpa16(d+GSM_PLANE,         gAl + (kc)*32); \
    cpa16(d+GSM_PLANE+16,      gAl + (kc)*32 + 8); \
    cpa16(d+2*GSM_PLANE,       gWh + (kc)*32); \
    cpa16(d+2*GSM_PLANE+16,    gWh + (kc)*32 + 8); \
    cpa16(d+3*GSM_PLANE,       gWl + (kc)*32); \
    cpa16(d+3*GSM_PLANE+16,    gWl + (kc)*32 + 8); \
    asm volatile("cp.async.commit_group;"); \
} while (0)

    int nch = K / 32;
    ISSUE(0, 0);
    if (nch > 1) ISSUE(1, 1);

    for (int c = 0; c < nch; c++) {
        int cur = c & 1;
        if (c + 1 < nch) asm volatile("cp.async.wait_group 1;");
        else             asm volatile("cp.async.wait_group 0;");
        __syncthreads();

        unsigned pah = sbase + cur*GSM_BUF + aoff;
        unsigned pal = pah + GSM_PLANE;
        unsigned pbh = sbase + cur*GSM_BUF + 2*GSM_PLANE + boff;
        unsigned pbl = pbh + GSM_PLANE;
#pragma unroll
        for (int ks = 0; ks < 2; ks++) {
            unsigned kb = ks*32;
            unsigned bh0[4], bh1[4], bl0[4], bl1[4];
            {
                unsigned r0,r1,r2,r3;
                ldsm4(r0,r1,r2,r3, pbh + kb);
                bh0[0]=r0; bh1[0]=r1; bh0[1]=r2; bh1[1]=r3;
                ldsm4(r0,r1,r2,r3, pbh + 1280 + kb);
                bh0[2]=r0; bh1[2]=r1; bh0[3]=r2; bh1[3]=r3;
                ldsm4(r0,r1,r2,r3, pbl + kb);
                bl0[0]=r0; bl1[0]=r1; bl0[1]=r2; bl1[1]=r3;
                ldsm4(r0,r1,r2,r3, pbl + 1280 + kb);
                bl0[2]=r0; bl1[2]=r1; bl0[3]=r2; bl1[3]=r3;
            }
#pragma unroll
            for (int im = 0; im < 4; im++) {
                unsigned ah0,ah1,ah2,ah3, al0,al1,al2,al3;
                ldsm4(ah0,ah1,ah2,ah3, pah + im*1280 + kb);
                ldsm4(al0,al1,al2,al3, pal + im*1280 + kb);
#pragma unroll
                for (int in = 0; in < 4; in++) {
                    mma_bf16(acc[im][in], ah0,ah1,ah2,ah3, bh0[in], bh1[in]);
                    mma_bf16(acc[im][in], ah0,ah1,ah2,ah3, bl0[in], bl1[in]);
                    mma_bf16(acc[im][in], al0,al1,al2,al3, bh0[in], bh1[in]);
                }
            }
        }
        __syncthreads();
        if (c + 2 < nch) ISSUE(cur, c + 2);
    }
#undef ISSUE

    // epilogue
#pragma unroll
    for (int im = 0; im < 4; im++) {
        int r0 = bm + warp_m*64 + im*16 + qq;
#pragma unroll
        for (int in = 0; in < 4; in++) {
            int c0 = bn + warp_n*32 + in*8 + 2*rr;
            float b0v = bias ? bias[c0]   : 0.f;
            float b1v = bias ? bias[c0+1] : 0.f;
#pragma unroll
            for (int half = 0; half < 2; half++) {
                int m = r0 + half*8;
                float v0 = acc[im][in][2*half + 0];
                float v1 = acc[im][in][2*half + 1];
                if (transv) {
                    size_t i0 = ((size_t)((m>>10)*HH + (c0>>6))*HD + (c0&63))*SS + (m&1023);
                    size_t i1 = ((size_t)((m>>10)*HH + ((c0+1)>>6))*HD + ((c0+1)&63))*SS + (m&1023);
                    split_store(v0 + b0v, Chi, Clo, i0);
                    split_store(v1 + b1v, Chi, Clo, i1);
                } else {
                    size_t idx = (size_t)m * N + c0;
                    float f0, f1;
                    if (accumulate) { f0 = C[idx] + v0; f1 = C[idx+1] + v1; }
                    else            { f0 = v0 + b0v;    f1 = v1 + b1v; }
                    if (C) { C[idx] = f0; C[idx+1] = f1; }
                    if (Chi) {
                        split_store(f0, Chi, Clo, idx);
                        split_store(f1, Chi, Clo, idx+1);
                    }
                }
            }
        }
    }
}

// ---------------- Global causal attention (bf16x3 MMA, pre-split QKV) -----
#define AW 36
#define A_QH 0
#define A_QL 2304
#define A_KH 4608
#define A_KL 6912
#define A_PH 9216
#define A_PL 11520
#define A_ST 13824               // float [64][66]
#define A_MS (13824 + 4224)
#define ATT_SMEM_WORDS (13824 + 4224 + 192)
#define ATT_SMEM_BYTES (ATT_SMEM_WORDS*4)

__global__ void __launch_bounds__(256) attn_global_mma()
{
    extern __shared__ unsigned usm[];
    float* STm = (float*)(usm + A_ST);
    float* m_s = (float*)(usm + A_MS);
    float* l_s = m_s + 64;
    float* al_s = l_s + 64;

    int qt = 15 - (int)blockIdx.x;
    int bh = blockIdx.y;
    int b = bh >> 4, h = bh & 15;
    int t = threadIdx.x;
    int lane = t & 31, wid = t >> 5;
    int tx = t & 15, ty = t >> 4;
    int warp_m = wid & 3, warp_n = wid >> 2;
    int qq = lane >> 2, rr = lane & 3;
    int q0 = qt * 64;
    size_t baseQ = (size_t)b * SS * DD + h * HD;
    size_t baseVT = ((size_t)(b*HH + h)) * HD * SS;

    // load Q tile hi/lo (rows q, 4 bf16 per thread per row)
#pragma unroll
    for (int i = 0; i < 4; i++) {
        int r = ty + 16*i;
        size_t gi = baseQ + (size_t)(q0 + r) * DD + 4*tx;
        uint2 vh = *(const uint2*)(gb_q_h + gi);
        uint2 vl = *(const uint2*)(gb_q_l + gi);
        usm[A_QH + r*AW + 2*tx] = vh.x;  usm[A_QH + r*AW + 2*tx + 1] = vh.y;
        usm[A_QL + r*AW + 2*tx] = vl.x;  usm[A_QL + r*AW + 2*tx + 1] = vl.y;
    }
    if (t < 64) { m_s[t] = -3.0e38f; l_s[t] = 0.f; }

    float oacc[4][4];
#pragma unroll
    for (int nn = 0; nn < 4; nn++)
#pragma unroll
        for (int r = 0; r < 4; r++) oacc[nn][r] = 0.f;

    __syncthreads();

    for (int kt = 0; kt <= qt; kt++) {
        int k0 = kt * 64;
        // 1) K tile hi/lo
#pragma unroll
        for (int i = 0; i < 4; i++) {
            int r = ty + 16*i;
            size_t gi = baseQ + (size_t)(k0 + r) * DD + 4*tx;
            uint2 vh = *(const uint2*)(gb_k_h + gi);
            uint2 vl = *(const uint2*)(gb_k_l + gi);
            usm[A_KH + r*AW + 2*tx] = vh.x;  usm[A_KH + r*AW + 2*tx + 1] = vh.y;
            usm[A_KL + r*AW + 2*tx] = vl.x;  usm[A_KL + r*AW + 2*tx + 1] = vl.y;
        }
        __syncthreads();

        // 2) S^T = K @ Q^T
        {
            float c4[4][4];
#pragma unroll
            for (int nn = 0; nn < 4; nn++)
#pragma unroll
                for (int r = 0; r < 4; r++) c4[nn][r] = 0.f;
#pragma unroll
            for (int ks = 0; ks < 4; ks++) {
                int kw = ks*8;
                int ar = warp_m*16 + qq;
                unsigned ah0 = usm[A_KH +  ar   *AW + kw+rr];
                unsigned ah1 = usm[A_KH + (ar+8)*AW + kw+rr];
                unsigned ah2 = usm[A_KH +  ar   *AW + kw+4+rr];
                unsigned ah3 = usm[A_KH + (ar+8)*AW + kw+4+rr];
                unsigned al0 = usm[A_KL +  ar   *AW + kw+rr];
                unsigned al1 = usm[A_KL + (ar+8)*AW + kw+rr];
                unsigned al2 = usm[A_KL +  ar   *AW + kw+4+rr];
                unsigned al3 = usm[A_KL + (ar+8)*AW + kw+4+rr];
#pragma unroll
                for (int nn = 0; nn < 4; nn++) {
                    int br = warp_n*32 + nn*8 + qq;
                    unsigned bh0 = usm[A_QH + br*AW + kw+rr];
                    unsigned bh1 = usm[A_QH + br*AW + kw+4+rr];
                    unsigned bl0 = usm[A_QL + br*AW + kw+rr];
                    unsigned bl1 = usm[A_QL + br*AW + kw+4+rr];
                    mma_bf16(c4[nn], ah0, ah1, ah2, ah3, bh0, bh1);
                    mma_bf16(c4[nn], ah0, ah1, ah2, ah3, bl0, bl1);
                    mma_bf16(c4[nn], al0, al1, al2, al3, bh0, bh1);
                }
            }
            int krow = warp_m*16 + qq;
#pragma unroll
            for (int nn = 0; nn < 4; nn++) {
                int qc = warp_n*32 + nn*8 + 2*rr;
                STm[ krow   *66 + qc    ] = c4[nn][0];
                STm[ krow   *66 + qc + 1] = c4[nn][1];
                STm[(krow+8)*66 + qc    ] = c4[nn][2];
                STm[(krow+8)*66 + qc + 1] = c4[nn][3];
            }
        }
        // 3) V tile loads (pre-split, transposed [d][s])
        uint2 vh[4], vl[4];
#pragma unroll
        for (int i = 0; i < 4; i++) {
            int d = ty + 16*i;
            size_t gi = baseVT + (size_t)d * SS + k0 + 4*tx;
            vh[i] = *(const uint2*)(gb_v_h + gi);
            vl[i] = *(const uint2*)(gb_v_l + gi);
        }
        __syncthreads();

        // 4) online softmax: row=q (t>>2), 4 lanes per row, 16 keys each
        {
            int row = t >> 2, sub = t & 3;
            int qglob = q0 + row;
            float mo = m_s[row];
            float mx = mo;
            float ev[16];
#pragma unroll
            for (int j2 = 0; j2 < 16; j2++) {
                int key = sub*16 + j2;
                float sv = STm[key*66 + row] * 0.125f;
                if (k0 + key > qglob) sv = -1.0e30f;
                ev[j2] = sv;
                mx = fmaxf(mx, sv);
            }
            mx = fmaxf(mx, __shfl_xor_sync(0xffffffffu, mx, 1));
            mx = fmaxf(mx, __shfl_xor_sync(0xffffffffu, mx, 2));
            float sum = 0.f;
#pragma unroll
            for (int j2 = 0; j2 < 16; j2++) {
                float e = __expf(ev[j2] - mx);
                ev[j2] = e; sum += e;
            }
#pragma unroll
            for (int j2 = 0; j2 < 8; j2++) {
                unsigned hi, lo;
                split_pack(ev[2*j2], ev[2*j2+1], hi, lo);
                usm[A_PH + row*AW + sub*8 + j2] = hi;
                usm[A_PL + row*AW + sub*8 + j2] = lo;
            }
            sum += __shfl_xor_sync(0xffffffffu, sum, 1);
            sum += __shfl_xor_sync(0xffffffffu, sum, 2);
            if (sub == 0) {
                float alpha = __expf(mo - mx);
                m_s[row] = mx;
                l_s[row] = l_s[row] * alpha + sum;
                al_s[row] = alpha;
            }
        }
        // 5) store V tile into KH/KL
#pragma unroll
        for (int i = 0; i < 4; i++) {
            int d = ty + 16*i;
            usm[A_KH + d*AW + 2*tx] = vh[i].x;  usm[A_KH + d*AW + 2*tx + 1] = vh[i].y;
            usm[A_KL + d*AW + 2*tx] = vl[i].x;  usm[A_KL + d*AW + 2*tx + 1] = vl[i].y;
        }
        __syncthreads();

        // 6) O *= alpha ; O += P @ V
        {
            int qr = warp_m*16 + qq;
            float a0 = al_s[qr], a1 = al_s[qr + 8];
#pragma unroll
            for (int nn = 0; nn < 4; nn++) {
                oacc[nn][0] *= a0; oacc[nn][1] *= a0;
                oacc[nn][2] *= a1; oacc[nn][3] *= a1;
            }
#pragma unroll
            for (int ks = 0; ks < 4; ks++) {
                int kw = ks*8;
                int ar = warp_m*16 + qq;
                unsigned ah0 = usm[A_PH +  ar   *AW + kw+rr];
                unsigned ah1 = usm[A_PH + (ar+8)*AW + kw+rr];
                unsigned ah2 = usm[A_PH +  ar   *AW + kw+4+rr];
                unsigned ah3 = usm[A_PH + (ar+8)*AW + kw+4+rr];
                unsigned al0 = usm[A_PL +  ar   *AW + kw+rr];
                unsigned al1 = usm[A_PL + (ar+8)*AW + kw+rr];
                unsigned al2 = usm[A_PL +  ar   *AW + kw+4+rr];
                unsigned al3 = usm[A_PL + (ar+8)*AW + kw+4+rr];
#pragma unroll
                for (int nn = 0; nn < 4; nn++) {
                    int br = warp_n*32 + nn*8 + qq;
                    unsigned bh0 = usm[A_KH + br*AW + kw+rr];
                    unsigned bh1 = usm[A_KH + br*AW + kw+4+rr];
                    unsigned bl0 = usm[A_KL + br*AW + kw+rr];
                    unsigned bl1 = usm[A_KL + br*AW + kw+4+rr];
                    mma_bf16(oacc[nn], ah0, ah1, ah2, ah3, bh0, bh1);
                    mma_bf16(oacc[nn], ah0, ah1, ah2, ah3, bl0, bl1);
                    mma_bf16(oacc[nn], al0, al1, al2, al3, bh0, bh1);
                }
            }
        }
        __syncthreads();
    }

    // write O hi/lo (normalized)
    {
        int qr = warp_m*16 + qq;
        float inv0 = 1.f / l_s[qr];
        float inv1 = 1.f / l_s[qr + 8];
#pragma unroll
        for (int nn = 0; nn < 4; nn++) {
            int dc = warp_n*32 + nn*8 + 2*rr;
            size_t i0 = baseQ + (size_t)(q0 + qr) * DD + dc;
            size_t i1 = baseQ + (size_t)(q0 + qr + 8) * DD + dc;
            split_store(oacc[nn][0] * inv0, gb_attn_h, gb_attn_l, i0);
            split_store(oacc[nn][1] * inv0, gb_attn_h, gb_attn_l, i0+1);
            split_store(oacc[nn][2] * inv1, gb_attn_h, gb_attn_l, i1);
            split_store(oacc[nn][3] * inv1, gb_attn_h, gb_attn_l, i1+1);
        }
    }
}

// ---------------- Predictor (two-stage, parallel, deterministic) ----------
__global__ void pred_partA()
{
    int b = blockIdx.x, ch = blockIdx.y;
    int t = threadIdx.x;
#pragma unroll
    for (int c = 0; c < 4; c++) {
        int col = t + 256*c;
        float s = 0.f;
        const float* p = g_gout + ((size_t)b*SS + ch*64) * DD + col;
        for (int r = 0; r < 64; r++) s += p[(size_t)r * DD];
        g_pp[((size_t)b*16 + ch)*DD + col] = s;
    }
}

__global__ void pred_partB(const float* __restrict__ Wp, const float* __restrict__ bp)
{
    __shared__ float red[256];
    int b = blockIdx.x;
    int t = threadIdx.x;
    float part = 0.f;
#pragma unroll
    for (int c = 0; c < 4; c++) {
        int col = t + 256*c;
        float s = 0.f;
#pragma unroll
        for (int ch = 0; ch < 16; ch++)
            s += g_pp[((size_t)b*16 + ch)*DD + col];
        part += (s * (1.0f/SS)) * Wp[col];
    }
    red[t] = part; __syncthreads();
    for (int o = 128; o > 0; o >>= 1) { if (t < o) red[t] += red[t+o]; __syncthreads(); }
    if (t == 0) {
        float z = red[0] + bp[0];
        g_base[b] = 1.f / (1.f + expf(-z));
    }
}

// ---------------- Span params ----------------
__global__ void params_kernel()
{
    float smf = (g_base[0] + g_base[1] + g_base[2] + g_base[3]) * 0.25f;
    double sm = (double)smf;
    int win = (int)(256.0 * sm);      if (win < 1) win = 1;
    int span_len = (int)(512.0 * sm); if (span_len < 1) span_len = 1;
    int lm = 512;
    if (span_len < lm) lm = span_len;
    if (win < lm) lm = win;
    g_params.win = win;
    g_params.span_len = span_len;
    g_params.local_max = lm;
    g_params.span_mean = smf;
    g_params.temp = (float)(1.0 + 0.01 * (1.0 - sm));
}

// ---------------- Local span attention (K == V) ----------------
__global__ void __launch_bounds__(256) attn_local_kernel()
{
    __shared__ float Qs[32][65];
    __shared__ float Ks[64][65];
    __shared__ float Ss[32][65];
    __shared__ float m_s[32], l_s[32], alpha_s[32];

    SpanParams p = g_params;
    int bh = blockIdx.x;  int b = bh >> 4, h = bh & 15;
    int qt = blockIdx.y;
    int t = threadIdx.x;
    int tx = t & 15, ty = t >> 4;
    size_t base = (size_t)b * SS * DD + h * HD;
    float sc = 0.35355339059327373f / p.temp;

    for (int w = blockIdx.z; w * p.win < SS; w += (int)gridDim.z) {
        int st = w * p.win;
        int en = st + p.win; if (en > SS) en = SS;
        int wlen = en - st;
        int ks0 = st - p.span_len + p.win; if (ks0 < 0) ks0 = 0;
        int ke = st + p.span_len; if (ke > SS) ke = SS;
        int klen = ke - ks0;
        int eff = (int)((double)wlen * (double)p.span_mean);
        if (eff > wlen) eff = wlen;
        if (eff > klen) eff = klen;
        if (eff > p.local_max) eff = p.local_max;
        int q0 = qt * 32;
        if (eff <= 0 || q0 >= eff) continue;
        int qcnt = eff - q0; if (qcnt > 32) qcnt = 32;

        {
            int col = tx * 4;
#pragma unroll
            for (int rr2 = 0; rr2 < 2; rr2++) {
                int r = ty + rr2*16;
                float4 qv = make_float4(0.f,0.f,0.f,0.f);
                if (r < qcnt)
                    qv = *(const float4*)(g_local + base + (size_t)(st + q0 + r) * DD + col);
                Qs[r][col+0]=qv.x; Qs[r][col+1]=qv.y; Qs[r][col+2]=qv.z; Qs[r][col+3]=qv.w;
            }
        }
        if (t < 32) { m_s[t] = -3.0e38f; l_s[t] = 0.f; }
        float accO[2][4];
#pragma unroll
        for (int i = 0; i < 2; i++)
#pragma unroll
            for (int j = 0; j < 4; j++) accO[i][j] = 0.f;
        __syncthreads();

        int nkt = (eff + 63) >> 6;
        for (int kt = 0; kt < nkt; kt++) {
            {
                int col = tx * 4;
#pragma unroll
                for (int rr2 = 0; rr2 < 4; rr2++) {
                    int r = ty + rr2*16;
                    float4 kv = make_float4(0.f,0.f,0.f,0.f);
                    if (kt*64 + r < eff)
                        kv = *(const float4*)(g_local + base + (size_t)(ks0 + kt*64 + r) * DD + col);
                    Ks[r][col+0]=kv.x; Ks[r][col+1]=kv.y; Ks[r][col+2]=kv.z; Ks[r][col+3]=kv.w;
                }
            }
            __syncthreads();
            float sacc[2][4];
#pragma unroll
            for (int i = 0; i < 2; i++)
#pragma unroll
                for (int j = 0; j < 4; j++) sacc[i][j] = 0.f;
#pragma unroll 8
            for (int kk = 0; kk < 64; kk++) {
                float qv0 = Qs[2*ty+0][kk];
                float qv1 = Qs[2*ty+1][kk];
#pragma unroll
                for (int j = 0; j < 4; j++) {
                    float kv = Ks[4*tx+j][kk];
                    sacc[0][j] += qv0*kv;
                    sacc[1][j] += qv1*kv;
                }
            }
#pragma unroll
            for (int i = 0; i < 2; i++) {
#pragma unroll
                for (int j = 0; j < 4; j++) {
                    float sv = sacc[i][j] * sc;
                    if (kt*64 + 4*tx + j >= eff) sv = -1.0e30f;
                    Ss[2*ty+i][4*tx+j] = sv;
                }
            }
            __syncthreads();
            {
                int row = t >> 3, sub = t & 7;
                float mo = m_s[row];
                float mx = mo;
#pragma unroll
                for (int c = sub; c < 64; c += 8) mx = fmaxf(mx, Ss[row][c]);
                mx = fmaxf(mx, __shfl_xor_sync(0xffffffffu, mx, 1));
                mx = fmaxf(mx, __shfl_xor_sync(0xffffffffu, mx, 2));
                mx = fmaxf(mx, __shfl_xor_sync(0xffffffffu, mx, 4));
                float sum = 0.f;
#pragma unroll
                for (int c = sub; c < 64; c += 8) {
                    float e = __expf(Ss[row][c] - mx);
                    Ss[row][c] = e; sum += e;
                }
                sum += __shfl_xor_sync(0xffffffffu, sum, 1);
                sum += __shfl_xor_sync(0xffffffffu, sum, 2);
                sum += __shfl_xor_sync(0xffffffffu, sum, 4);
                if (sub == 0) {
                    float alpha = __expf(mo - mx);
                    m_s[row] = mx;
                    l_s[row] = l_s[row]*alpha + sum;
                    alpha_s[row] = alpha;
                }
            }
            __syncthreads();
#pragma unroll
            for (int i = 0; i < 2; i++) {
                float al = alpha_s[2*ty+i];
#pragma unroll
                for (int j = 0; j < 4; j++) accO[i][j] *= al;
            }
#pragma unroll 4
            for (int c = 0; c < 64; c++) {
                float p0 = Ss[2*ty+0][c];
                float p1 = Ss[2*ty+1][c];
#pragma unroll
                for (int j = 0; j < 4; j++) {
                    float vv = Ks[c][4*tx+j];
                    accO[0][j] += p0*vv;
                    accO[1][j] += p1*vv;
                }
            }
            __syncthreads();
        }
#pragma unroll
        for (int i = 0; i < 2; i++) {
            int r = 2*ty + i;
            if (r < qcnt) {
                float inv = 1.f / l_s[r];
#pragma unroll
                for (int j = 0; j < 4; j++) {
                    size_t idx = base + (size_t)(st + q0 + r) * DD + 4*tx + j;
                    split_store(accO[i][j] * inv, gb_lout_h, gb_lout_l, idx);
                }
            }
        }
        __syncthreads();
    }
}

// ---------------- launch ----------------
extern "C" void kernel_launch(void* const* d_in, const int* in_sizes, int n_in,
                              void* d_out, int out_size)
{
    const float* x     = (const float*)d_in[0];
    const float* ln_ag = (const float*)d_in[1];
    const float* ln_ab = (const float*)d_in[2];
    const float* ln_bg = (const float*)d_in[3];
    const float* ln_bb = (const float*)d_in[4];
    const float* Wq    = (const float*)d_in[5];
    const float* bq    = (const float*)d_in[6];
    const float* Wk    = (const float*)d_in[7];
    const float* Wv    = (const float*)d_in[8];
    const float* bv    = (const float*)d_in[9];
    const float* Wo    = (const float*)d_in[10];
    const float* bo    = (const float*)d_in[11];
    const float* Wp    = (const float*)d_in[12];
    const float* bp    = (const float*)d_in[13];
    const float* Wproj = (const float*)d_in[14];
    const float* bproj = (const float*)d_in[15];
    float* out = (float*)d_out;

    // symbol addresses
    void *p_gout, *p_lh, *p_ll;
    void *p_gh, *p_gl, *p_qh, *p_ql, *p_kh, *p_kl, *p_vh, *p_vl;
    void *p_ah, *p_al, *p_oh, *p_ol;
    void *p_wqh, *p_wql, *p_wkh, *p_wkl, *p_wvh, *p_wvl, *p_woh, *p_wol, *p_wph, *p_wpl;
    cudaGetSymbolAddress(&p_gout, g_gout);
    cudaGetSymbolAddress(&p_lh, gb_lout_h);  cudaGetSymbolAddress(&p_ll, gb_lout_l);
    cudaGetSymbolAddress(&p_gh, gb_globe_h); cudaGetSymbolAddress(&p_gl, gb_globe_l);
    cudaGetSymbolAddress(&p_qh, gb_q_h);     cudaGetSymbolAddress(&p_ql, gb_q_l);
    cudaGetSymbolAddress(&p_kh, gb_k_h);     cudaGetSymbolAddress(&p_kl, gb_k_l);
    cudaGetSymbolAddress(&p_vh, gb_v_h);     cudaGetSymbolAddress(&p_vl, gb_v_l);
    cudaGetSymbolAddress(&p_ah, gb_attn_h);  cudaGetSymbolAddress(&p_al, gb_attn_l);
    cudaGetSymbolAddress(&p_oh, gb_gout_h);  cudaGetSymbolAddress(&p_ol, gb_gout_l);
    cudaGetSymbolAddress(&p_wqh, gb_wq_h);   cudaGetSymbolAddress(&p_wql, gb_wq_l);
    cudaGetSymbolAddress(&p_wkh, gb_wk_h);   cudaGetSymbolAddress(&p_wkl, gb_wk_l);
    cudaGetSymbolAddress(&p_wvh, gb_wv_h);   cudaGetSymbolAddress(&p_wvl, gb_wv_l);
    cudaGetSymbolAddress(&p_woh, gb_wo_h);   cudaGetSymbolAddress(&p_wol, gb_wo_l);
    cudaGetSymbolAddress(&p_wph, gb_wp_h);   cudaGetSymbolAddress(&p_wpl, gb_wp_l);

    cudaFuncSetAttribute(gemm_bf16lm, cudaFuncAttributeMaxDynamicSharedMemorySize, GEMM_SMEM_BYTES);
    cudaFuncSetAttribute(attn_global_mma, cudaFuncAttributeMaxDynamicSharedMemorySize, ATT_SMEM_BYTES);

    // 0) weight splits
    const int W1M4 = DD*DD/4, W2M4 = DD*2*DD/4;
    conv_split<<<(W1M4+255)/256, 256>>>((const float4*)Wq, (__nv_bfloat16*)p_wqh, (__nv_bfloat16*)p_wql, W1M4);
    conv_split<<<(W1M4+255)/256, 256>>>((const float4*)Wk, (__nv_bfloat16*)p_wkh, (__nv_bfloat16*)p_wkl, W1M4);
    conv_split<<<(W1M4+255)/256, 256>>>((const float4*)Wv, (__nv_bfloat16*)p_wvh, (__nv_bfloat16*)p_wvl, W1M4);
    conv_split<<<(W1M4+255)/256, 256>>>((const float4*)Wo, (__nv_bfloat16*)p_woh, (__nv_bfloat16*)p_wol, W1M4);
    conv_split<<<(W2M4+255)/256, 256>>>((const float4*)Wproj, (__nv_bfloat16*)p_wph, (__nv_bfloat16*)p_wpl, W2M4);

    // 1) LayerNorms
    ln_kernel<<<MROWS, 256>>>(x, ln_ag, ln_ab, ln_bg, ln_bb);

    // 2) QKV projections (bf16 hi/lo outputs; V transposed)
    dim3 ggrid(DD/128, MROWS/128);
    gemm_bf16lm<<<ggrid, 256, GEMM_SMEM_BYTES>>>((__nv_bfloat16*)p_gh, (__nv_bfloat16*)p_gl,
        (__nv_bfloat16*)p_wqh, (__nv_bfloat16*)p_wql, bq, nullptr,
        (__nv_bfloat16*)p_qh, (__nv_bfloat16*)p_ql, DD, DD, DD, 0, 0, 0);
    gemm_bf16lm<<<ggrid, 256, GEMM_SMEM_BYTES>>>((__nv_bfloat16*)p_gh, (__nv_bfloat16*)p_gl,
        (__nv_bfloat16*)p_wkh, (__nv_bfloat16*)p_wkl, nullptr, nullptr,
        (__nv_bfloat16*)p_kh, (__nv_bfloat16*)p_kl, DD, DD, DD, 0, 0, 0);
    gemm_bf16lm<<<ggrid, 256, GEMM_SMEM_BYTES>>>((__nv_bfloat16*)p_gh, (__nv_bfloat16*)p_gl,
        (__nv_bfloat16*)p_wvh, (__nv_bfloat16*)p_wvl, bv, nullptr,
        (__nv_bfloat16*)p_vh, (__nv_bfloat16*)p_vl, DD, DD, DD, 0, 0, 1);

    // 3) Global causal attention
    attn_global_mma<<<dim3(16, BB*HH), 256, ATT_SMEM_BYTES>>>();

    // 4) Output projection (fp32 gout for predictor + hi/lo for Wproj)
    gemm_bf16lm<<<ggrid, 256, GEMM_SMEM_BYTES>>>((__nv_bfloat16*)p_ah, (__nv_bfloat16*)p_al,
        (__nv_bfloat16*)p_woh, (__nv_bfloat16*)p_wol, bo, (float*)p_gout,
        (__nv_bfloat16*)p_oh, (__nv_bfloat16*)p_ol, DD, DD, DD, 0, 0, 0);

    // 5) Span predictor + params
    pred_partA<<<dim3(BB, 16), 256>>>();
    pred_partB<<<BB, 256>>>(Wp, bp);
    params_kernel<<<1, 1>>>();

    // 6) Local span attention (zero hi/lo planes, then fill)
    const int NZ = MROWS*DD*2/16;  // uint4 count per bf16 plane
    zero_u4<<<(NZ+255)/256, 256>>>((uint4*)p_lh, NZ);
    zero_u4<<<(NZ+255)/256, 256>>>((uint4*)p_ll, NZ);
    attn_local_kernel<<<dim3(BB*HH, 8, 16), 256>>>();

    // 7) Final projection: out = [local_out, globe_out] @ Wproj^T + bproj
    gemm_bf16lm<<<ggrid, 256, GEMM_SMEM_BYTES>>>((__nv_bfloat16*)p_lh, (__nv_bfloat16*)p_ll,
        (__nv_bfloat16*)p_wph, (__nv_bfloat16*)p_wpl, bproj, out,
        nullptr, nullptr, DD, DD, 2*DD, 0, 0, 0);
    gemm_bf16lm<<<ggrid, 256, GEMM_SMEM_BYTES>>>((__nv_bfloat16*)p_oh, (__nv_bfloat16*)p_ol,
        (__nv_bfloat16*)p_wph, (__nv_bfloat16*)p_wpl, nullptr, out,
        nullptr, nullptr, DD, DD, 2*DD, DD, 1, 0);
}